// round 10
// baseline (speedup 1.0000x reference)
#include <cuda_runtime.h>
#include <math.h>
#include <stdint.h>

#define BS   4096
#define L    20
#define NF   128
#define DM   640
#define DIN  512
#define DH   320
#define NB3  384

// ---------------- scratch ----------------
__device__ float g_last [BS*DIN];
__device__ float g_wctx [BS*2*DM];
__device__ float g_qh   [BS*NF];
__device__ float g_qh2  [BS*NB3];
__device__ float g_A2   [BS*512];
__device__ float g_hpl  [BS*NF];
__device__ float g_gi   [BS*3*NF];
__device__ float g_gh   [BS*3*NF];
__device__ float g_hpr  [BS*NF];
__device__ float g_q2   [2*DM];
__device__ float g_G3   [NF*2*DM];     // (128,1280) N x K
__device__ float g_b3   [NF];
__device__ float g_WcmbT[NF*512];      // (128,512) N x K

__device__ __forceinline__ unsigned f2tf(float v) {
    unsigned r;
    asm("cvt.rna.tf32.f32 %0, %1;" : "=r"(r) : "f"(v));
    return r;
}

__device__ __forceinline__ uint32_t smem_u32(const void* p) {
    uint32_t a;
    asm("{ .reg .u64 t; cvta.to.shared.u64 t, %1; cvt.u32.u64 %0, t; }" : "=r"(a) : "l"(p));
    return a;
}
static __device__ __forceinline__ void cp16(uint32_t s, const void* g) {
    asm volatile("cp.async.cg.shared.global [%0], [%1], 16;" :: "r"(s), "l"(g));
}

__device__ __forceinline__ void mma_tf32(float c[4], unsigned a0, unsigned a1,
                                         unsigned a2, unsigned a3,
                                         unsigned b0, unsigned b1) {
    asm volatile(
        "mma.sync.aligned.m16n8k8.row.col.f32.tf32.tf32.f32 "
        "{%0,%1,%2,%3}, {%4,%5,%6,%7}, {%8,%9}, {%0,%1,%2,%3};"
        : "+f"(c[0]), "+f"(c[1]), "+f"(c[2]), "+f"(c[3])
        : "r"(a0), "r"(a1), "r"(a2), "r"(a3), "r"(b0), "r"(b1));
}

// ---------------- tf32 GEMM: C = A @ B^T (+bias), cp.async 3-stage ----------------
// RED=1: K-split via blockIdx.z (K = slice size, k-offset = z*K); epilogue atomicAdd,
//        bias must be pre-initialized into C.
#define GS 3
#define STG_F (128*20)
#define GEMM_SMEM (GS*2*STG_F*4)

template<int ACT, int RED>
__global__ __launch_bounds__(256, 2) void gemm_tc(
    const float* __restrict__ A, int lda,
    const float* __restrict__ B, int ldb,
    const float* __restrict__ bias,
    float* __restrict__ C, int ldc,
    int M, int N, int K)
{
    extern __shared__ float smem[];
    const uint32_t smb = smem_u32(smem);
    const int bm = blockIdx.y * 128;
    const int bn = blockIdx.x * 128;
    const size_t kofs = (size_t)blockIdx.z * K;
    const int t  = threadIdx.x;
    const int lane = t & 31;
    const int wr = (t >> 5) >> 2;
    const int wc = (t >> 5) & 3;
    const int g = lane >> 2, tig = lane & 3;

    const int niter = K >> 4;
    const float* Abase = A + (size_t)bm * lda + kofs;
    const float* Bbase = B + (size_t)bn * ldb + kofs;

    auto load_stage = [&](int s, int c) {
        uint32_t as = smb + (uint32_t)(s * 2 * STG_F) * 4;
        uint32_t bs = as + STG_F * 4;
        const float* Ac = Abase + c * 16;
        const float* Bc = Bbase + c * 16;
        #pragma unroll
        for (int i = 0; i < 2; i++) {
            int id = i * 256 + t;
            int row = id >> 2, seg = id & 3;
            cp16(as + (uint32_t)(row * 20 + seg * 4) * 4, Ac + (size_t)row * lda + seg * 4);
            cp16(bs + (uint32_t)(row * 20 + seg * 4) * 4, Bc + (size_t)row * ldb + seg * 4);
        }
    };

    float acc[4][4][4] = {};

    #pragma unroll
    for (int s = 0; s < GS - 1; s++) {
        if (s < niter) load_stage(s, s);
        asm volatile("cp.async.commit_group;" ::: "memory");
    }

    for (int c = 0; c < niter; c++) {
        asm volatile("cp.async.wait_group %0;" :: "n"(GS - 2) : "memory");
        __syncthreads();
        if (c + GS - 1 < niter) load_stage((c + GS - 1) % GS, c + GS - 1);
        asm volatile("cp.async.commit_group;" ::: "memory");

        const float* As  = smem + (c % GS) * 2 * STG_F;
        const float* Bsm = As + STG_F;
        #pragma unroll
        for (int s8 = 0; s8 < 2; s8++) {
            const int kk = s8 * 8;
            unsigned af[4][4]; unsigned bf[4][2];
            #pragma unroll
            for (int i = 0; i < 4; i++) {
                int r0 = (wr * 64 + i * 16 + g) * 20 + kk + tig;
                af[i][0] = f2tf(As[r0]);
                af[i][1] = f2tf(As[r0 + 8 * 20]);
                af[i][2] = f2tf(As[r0 + 4]);
                af[i][3] = f2tf(As[r0 + 8 * 20 + 4]);
            }
            #pragma unroll
            for (int j = 0; j < 4; j++) {
                int n0 = (wc * 32 + j * 8 + g) * 20 + kk + tig;
                bf[j][0] = f2tf(Bsm[n0]);
                bf[j][1] = f2tf(Bsm[n0 + 4]);
            }
            #pragma unroll
            for (int i = 0; i < 4; i++)
                #pragma unroll
                for (int j = 0; j < 4; j++)
                    mma_tf32(acc[i][j], af[i][0], af[i][1], af[i][2], af[i][3],
                             bf[j][0], bf[j][1]);
        }
    }

    #pragma unroll
    for (int i = 0; i < 4; i++) {
        int row = bm + wr * 64 + i * 16 + g;
        #pragma unroll
        for (int j = 0; j < 4; j++) {
            int col = bn + wc * 32 + j * 8 + tig * 2;
            if (RED) {
                atomicAdd(C + (size_t)row * ldc + col,           acc[i][j][0]);
                atomicAdd(C + (size_t)row * ldc + col + 1,       acc[i][j][1]);
                atomicAdd(C + (size_t)(row + 8) * ldc + col,     acc[i][j][2]);
                atomicAdd(C + (size_t)(row + 8) * ldc + col + 1, acc[i][j][3]);
            } else {
                float b0 = bias ? bias[col] : 0.f;
                float b1 = bias ? bias[col + 1] : 0.f;
                float v00 = acc[i][j][0] + b0, v01 = acc[i][j][1] + b1;
                float v10 = acc[i][j][2] + b0, v11 = acc[i][j][3] + b1;
                if (ACT == 1) { v00 = tanhf(v00); v01 = tanhf(v01);
                                v10 = tanhf(v10); v11 = tanhf(v11); }
                *(float2*)(C + (size_t)row * ldc + col)       = make_float2(v00, v01);
                *(float2*)(C + (size_t)(row + 8) * ldc + col) = make_float2(v10, v11);
            }
        }
    }
}

// ---------------- bias broadcast init (for split-K target) ----------------
__global__ void bias_init(const float* __restrict__ bias, float* __restrict__ C) {
    // grid BS, 128 threads
    C[(size_t)blockIdx.x * NF + threadIdx.x] = bias[threadIdx.x];
}

// ---------------- prep_q ----------------
__global__ void prep_q(const float* __restrict__ ipw, const float* __restrict__ ipb,
                       const float* __restrict__ time_b, float* __restrict__ q2)
{
    __shared__ float tc[NF];
    __shared__ float q0s[DH];
    int h = blockIdx.x, t = threadIdx.x;
    if (t < NF) tc[t] = cosf(time_b[t]);
    __syncthreads();
    if (t < DH) {
        int e = h*DH + t;
        float acc = ipb[e];
        const float* row = ipw + (size_t)e * DM + DIN;
        for (int k = 0; k < NF; k++) acc += tc[k] * row[k];
        q0s[t] = acc;
    }
    __syncthreads();
    float acc = 0.f;
    const float* base = ipw + (size_t)(DM + h*DH) * DM + t;
    for (int d = 0; d < DH; d++) acc += q0s[d] * base[(size_t)d * DM];
    q2[h*DM + t] = acc;
}

// ---------------- prep_G: G3 rows, b3, WcmbT ----------------
__global__ __launch_bounds__(256) void prep_G(
    const float* __restrict__ ipw, const float* __restrict__ ipb,
    const float* __restrict__ opw, const float* __restrict__ opb,
    const float* __restrict__ wf, const float* __restrict__ bf,
    const float* __restrict__ wq, const float* __restrict__ wv,
    const float* __restrict__ mw,
    float* __restrict__ G3, float* __restrict__ b3, float* __restrict__ WcmbT)
{
    int i = blockIdx.x, t = threadIdx.x;
    if (i >= 128) {
        int r = i - 128;
        if (r < 384) {
            if (t < NF) {
                float acc = 0.f;
                const float* wvr = wv + (size_t)r * NF;
                for (int k = 0; k < NF; k++) acc += wvr[k] * mw[k * NF + t];
                WcmbT[(size_t)t * 512 + r] = acc;
            }
        } else {
            int r2 = r - 384;
            if (t < NF) WcmbT[(size_t)t * 512 + 384 + r2] = mw[(NF + r2) * NF + t];
        }
        return;
    }
    __shared__ float wqc[NF];
    __shared__ float b1s[NF];
    __shared__ float t2[DM];
    __shared__ float gt[DM];
    __shared__ float red[256];
    if (t < NF) {
        wqc[t] = wq[t * NF + i];
        float acc = bf[t];
        const float* row = wf + (size_t)t * DM;
        for (int m = 0; m < DM; m++) acc += row[m] * opb[m];
        b1s[t] = acc;
    }
    __syncthreads();
    for (int j = t; j < DM; j += 256) {
        float acc = 0.f;
        for (int q = 0; q < NF; q++) acc += wqc[q] * wf[(size_t)q * DM + j];
        t2[j] = acc;
    }
    __syncthreads();
    for (int d = t; d < DM; d += 256) {
        float acc = 0.f;
        for (int m = 0; m < DM; m++) acc += t2[m] * opw[(size_t)m * DM + d];
        gt[d] = acc;
    }
    __syncthreads();
    for (int c = t; c < 2*DM; c += 256) {
        int h = c / DM, cc = c - h*DM;
        float acc = 0.f;
        const float* base = ipw + (size_t)(2*DM + h*DH) * DM + cc;
        const float* gth = gt + h*DH;
        for (int dd = 0; dd < DH; dd++) acc += gth[dd] * base[(size_t)dd * DM];
        G3[(size_t)i * (2*DM) + c] = acc;
    }
    float p = 0.f;
    for (int d = t; d < DM; d += 256) p += gt[d] * ipb[2*DM + d];
    if (t < NF) p += b1s[t] * wqc[t];
    red[t] = p;
    __syncthreads();
    if (t == 0) {
        float s = 0.f;
        for (int k = 0; k < 256; k++) s += red[k];
        b3[i] = s;
    }
}

// ---------------- MHA stage ----------------
#define MHA2_SMEM ((L*DM + 2*DM + 64) * 4 + L*5*4)
__global__ __launch_bounds__(256) void mha2_kernel(
    const int* __restrict__ nids, const int* __restrict__ hist_nids,
    const int* __restrict__ anon_ids, const int* __restrict__ hist_eids,
    const float* __restrict__ hist_ts, const int* __restrict__ hist_dirs,
    const float* __restrict__ node_feat, const float* __restrict__ edge_feat,
    const float* __restrict__ anony_emb, const float* __restrict__ time_w,
    const float* __restrict__ time_b, const float* __restrict__ q2,
    float* __restrict__ wctx, float* __restrict__ last)
{
    extern __shared__ float sm[];
    float* rows = sm;
    float* q2s  = sm + L*DM;
    float* sc   = q2s + 2*DM;
    int*   hn   = (int*)(sc + 64);
    int*   eid  = hn + L;
    int*   aid  = eid + L;
    int*   dirr = aid + L;
    float* dts  = (float*)(dirr + L);

    int b = blockIdx.x, t = threadIdx.x;
    if (t < L) {
        hn[t]  = hist_nids[b*L + t];
        eid[t] = hist_eids[b*L + t];
        aid[t] = anon_ids[b*L + t];
        dirr[t] = hist_dirs[b*L + t];
        dts[t] = hist_ts[b*L + L-1] - hist_ts[b*L + t];
    }
    for (int i = t; i < 2*DM; i += 256) q2s[i] = q2[i];
    __syncthreads();
    int nid = nids[b];

    for (int idx = t; idx < L*DM; idx += 256) {
        int m = idx / DM, d = idx - m*DM;
        float v;
        if (d < NF) {
            int src = dirr[m] ? nid : hn[m];
            v = node_feat[(size_t)src*NF + d];
        } else if (d < 2*NF) {
            int dst = dirr[m] ? hn[m] : nid;
            v = node_feat[(size_t)dst*NF + (d - NF)];
        } else if (d < 3*NF) {
            v = anony_emb[(size_t)aid[m]*NF + (d - 2*NF)];
        } else if (d < 4*NF) {
            v = edge_feat[(size_t)eid[m]*NF + (d - 3*NF)];
        } else {
            int f = d - 4*NF;
            v = cosf(fmaf(dts[m], time_w[f], time_b[f]));
        }
        if (m == L-1 && d < DIN) {
            last[(size_t)b*DIN + d] = v;
            v = 0.f;
        }
        rows[idx] = v;
    }
    __syncthreads();

    int w = t >> 5, lane = t & 31;
    for (int p = w; p < 2*L; p += 8) {
        int h = p / L, m = p - h*L;
        const float* qp = q2s + h*DM;
        const float* rp = rows + m*DM;
        float s = 0.f;
        for (int d = lane; d < DM; d += 32) s += qp[d] * rp[d];
        #pragma unroll
        for (int o = 16; o; o >>= 1) s += __shfl_xor_sync(0xffffffffu, s, o);
        if (lane == 0) {
            bool msk = (hn[m] == 0) && (m != L-1);
            sc[h*L + m] = msk ? -1e9f : s * (1.f / sqrtf((float)DH));
        }
    }
    __syncthreads();
    if (t < 2) {
        float mx = -1e30f;
        for (int m = 0; m < L; m++) mx = fmaxf(mx, sc[t*L + m]);
        float sum = 0.f;
        for (int m = 0; m < L; m++) { float e = expf(sc[t*L + m] - mx); sc[t*L + m] = e; sum += e; }
        float inv = 1.f / sum;
        for (int m = 0; m < L; m++) sc[t*L + m] *= inv;
    }
    __syncthreads();
    for (int i = t; i < 2*DM; i += 256) {
        int h = i / DM, d = i - h*DM;
        float acc = 0.f;
        #pragma unroll
        for (int m = 0; m < L; m++) acc += sc[h*L + m] * rows[m*DM + d];
        wctx[(size_t)b*(2*DM) + i] = acc;
    }
}

// ---------------- pooling attention stage ----------------
#define ATT2_SMEM ((L*NB3 + NB3 + 32) * 4 + L*3*4)
__global__ __launch_bounds__(128) void attn2_kernel(
    const int* __restrict__ nids, const int* __restrict__ hist_nids,
    const int* __restrict__ hist_eids, const float* __restrict__ hist_ts,
    const float* __restrict__ node_feat, const float* __restrict__ edge_feat,
    const float* __restrict__ time_w, const float* __restrict__ time_b,
    const float* __restrict__ qh2,
    float* __restrict__ A2)
{
    extern __shared__ float sm[];
    float* rows = sm;
    float* qs   = sm + L*NB3;
    float* a    = qs + NB3;
    int*   hn   = (int*)(a + 32);
    int*   eid  = hn + L;
    float* dts  = (float*)(eid + L);

    int b = blockIdx.x, t = threadIdx.x;
    if (t < L) {
        hn[t]  = hist_nids[b*L + t];
        eid[t] = hist_eids[b*L + t];
        dts[t] = hist_ts[b*L + L-1] - hist_ts[b*L + t];
    }
    for (int i = t; i < NB3; i += 128) qs[i] = qh2[(size_t)b*NB3 + i];
    __syncthreads();

    for (int idx = t; idx < L*NB3; idx += 128) {
        int m = idx / NB3, d = idx - m*NB3;
        float v;
        if (d < NF)          v = node_feat[(size_t)hn[m]*NF + d];
        else if (d < 2*NF)   v = edge_feat[(size_t)eid[m]*NF + (d - NF)];
        else {
            int f = d - 2*NF;
            v = cosf(fmaf(dts[m], time_w[f], time_b[f]));
        }
        rows[idx] = v;
    }
    __syncthreads();

    int w = t >> 5, lane = t & 31;
    for (int l = w; l < L; l += 4) {
        const float* rp = rows + l*NB3;
        float s = 0.f;
        for (int d = lane; d < NB3; d += 32) s += qs[d] * rp[d];
        #pragma unroll
        for (int o = 16; o; o >>= 1) s += __shfl_xor_sync(0xffffffffu, s, o);
        if (lane == 0) {
            bool msk = (hn[l] == 0) && (l != L-1);
            a[l] = msk ? -1e9f : s * (1.f / sqrtf((float)NF));
        }
    }
    __syncthreads();
    if (t == 0) {
        float mx = -1e30f;
        for (int l = 0; l < L; l++) mx = fmaxf(mx, a[l]);
        float sum = 0.f;
        for (int l = 0; l < L; l++) { float e = expf(a[l] - mx); a[l] = e; sum += e; }
        float inv = 1.f / sum;
        for (int l = 0; l < L; l++) a[l] *= inv;
    }
    __syncthreads();
    for (int d = t; d < NB3; d += 128) {
        float acc = 0.f;
        #pragma unroll
        for (int l = 0; l < L; l++) acc += a[l] * rows[l*NB3 + d];
        A2[(size_t)b*512 + d] = acc;
    }
    A2[(size_t)b*512 + NB3 + t] = node_feat[(size_t)nids[b]*NF + t];
}

// ---------------- GRU ----------------
__global__ void gru_kernel(const float* __restrict__ gi, const float* __restrict__ gh,
                           const float* __restrict__ hpl, float* __restrict__ hpr)
{
    int idx = blockIdx.x * blockDim.x + threadIdx.x;
    if (idx >= BS*NF) return;
    int b = idx / NF, f = idx - b*NF;
    const float* gib = gi + (size_t)b*3*NF;
    const float* ghb = gh + (size_t)b*3*NF;
    float r = 1.f / (1.f + expf(-(gib[f]      + ghb[f])));
    float z = 1.f / (1.f + expf(-(gib[NF + f] + ghb[NF + f])));
    float n = tanhf(gib[2*NF + f] + r * ghb[2*NF + f]);
    hpr[idx] = (1.f - z) * n + z * hpl[idx];
}

// ---------------- RK4 ODE: 4-acc dot, double-buffered vs (1 sync/feval) ----------------
#define ODE_SMEM ((128*129 + 2*128) * 4)
__global__ __launch_bounds__(128) void ode_kernel(
    const float* __restrict__ hpr, const float* __restrict__ ode_w,
    const float* __restrict__ ode_b, const float* __restrict__ tnode_w,
    const float* __restrict__ tnode_b, const float* __restrict__ hist_ts,
    float* __restrict__ out)
{
    extern __shared__ float sm[];
    float* Wsm = sm;
    float* vs  = sm + 128*129;       // two buffers of 128
    int b = blockIdx.x, f = threadIdx.x;
    for (int i = f; i < NF*NF; i += 128) Wsm[(i >> 7)*129 + (i & 127)] = ode_w[i];
    float t0 = hist_ts[b*L + L-2];
    float t1 = hist_ts[b*L + L-1];
    float ratio = t1 - t0;
    float twf = tnode_w[f], tbf = tnode_b[f], obf = ode_b[f];
    float h0 = hpr[(size_t)b*NF + f];
    float z = h0;
    __syncthreads();
    float w[NF];
    #pragma unroll
    for (int k = 0; k < NF; k++) w[k] = Wsm[f*129 + k];
    __syncthreads();

    int buf = 0;
    auto feval = [&](float s, float zin) -> float {
        float* vb = vs + buf * 128;
        float t = fmaf(s, ratio, t0);
        vb[f] = zin + cosf(fmaf(t, twf, tbf));
        __syncthreads();
        float a0 = 0.f, a1 = 0.f, a2 = 0.f, a3 = 0.f;
        #pragma unroll
        for (int k = 0; k < NF; k += 16) {
            float4 v0 = *(const float4*)&vb[k];
            float4 v1 = *(const float4*)&vb[k+4];
            float4 v2 = *(const float4*)&vb[k+8];
            float4 v3 = *(const float4*)&vb[k+12];
            a0 += v0.x*w[k]    + v0.y*w[k+1]  + v0.z*w[k+2]  + v0.w*w[k+3];
            a1 += v1.x*w[k+4]  + v1.y*w[k+5]  + v1.z*w[k+6]  + v1.w*w[k+7];
            a2 += v2.x*w[k+8]  + v2.y*w[k+9]  + v2.z*w[k+10] + v2.w*w[k+11];
            a3 += v3.x*w[k+12] + v3.y*w[k+13] + v3.z*w[k+14] + v3.w*w[k+15];
        }
        buf ^= 1;                    // next feval writes the other buffer
        return tanhf(obf + ((a0 + a1) + (a2 + a3))) * ratio;
    };

    const float ds = 0.125f;
    for (int st = 0; st < 8; st++) {
        float s = st * ds;
        float k1 = feval(s,            z);
        float k2 = feval(s + 0.5f*ds,  z + 0.5f*ds*k1);
        float k3 = feval(s + 0.5f*ds,  z + 0.5f*ds*k2);
        float k4 = feval(s + ds,       z + ds*k3);
        z += ds * (1.f/6.f) * (k1 + 2.f*k2 + 2.f*k3 + k4);
    }
    out[(size_t)b*NF + f] = z;
    out[(size_t)BS*NF + (size_t)b*NF + f] = h0;
    if (f == 0) out[(size_t)2*BS*NF + b] = t1;
}

// ---------------- launch ----------------
extern "C" void kernel_launch(void* const* d_in, const int* in_sizes, int n_in,
                              void* d_out, int out_size)
{
    const int*   nids      = (const int*)  d_in[0];
    const int*   hist_nids = (const int*)  d_in[2];
    const int*   anon      = (const int*)  d_in[3];
    const int*   eids      = (const int*)  d_in[4];
    const float* hist_ts   = (const float*)d_in[5];
    const int*   dirs      = (const int*)  d_in[6];
    const float* node_feat = (const float*)d_in[7];
    const float* edge_feat = (const float*)d_in[8];
    const float* anony_emb = (const float*)d_in[9];
    const float* time_w    = (const float*)d_in[10];
    const float* time_b    = (const float*)d_in[11];
    const float* in_proj_w = (const float*)d_in[12];
    const float* in_proj_b = (const float*)d_in[13];
    const float* out_proj_w= (const float*)d_in[14];
    const float* out_proj_b= (const float*)d_in[15];
    const float* outfn_w   = (const float*)d_in[16];
    const float* outfn_b   = (const float*)d_in[17];
    const float* attn_wq   = (const float*)d_in[18];
    const float* attn_wk   = (const float*)d_in[19];
    const float* attn_wv   = (const float*)d_in[20];
    const float* merge_w   = (const float*)d_in[21];
    const float* merge_b   = (const float*)d_in[22];
    const float* gru_w_ih  = (const float*)d_in[23];
    const float* gru_w_hh  = (const float*)d_in[24];
    const float* gru_b_ih  = (const float*)d_in[25];
    const float* gru_b_hh  = (const float*)d_in[26];
    const float* ode_w     = (const float*)d_in[27];
    const float* ode_b     = (const float*)d_in[28];
    const float* tnode_w   = (const float*)d_in[29];
    const float* tnode_b   = (const float*)d_in[30];
    float* out = (float*)d_out;

    float *p_last, *p_wctx, *p_qh, *p_qh2, *p_A2, *p_hpl, *p_gi, *p_gh, *p_hpr,
          *p_q2, *p_G3, *p_b3, *p_WcmbT;
    cudaGetSymbolAddress((void**)&p_last,  g_last);
    cudaGetSymbolAddress((void**)&p_wctx,  g_wctx);
    cudaGetSymbolAddress((void**)&p_qh,    g_qh);
    cudaGetSymbolAddress((void**)&p_qh2,   g_qh2);
    cudaGetSymbolAddress((void**)&p_A2,    g_A2);
    cudaGetSymbolAddress((void**)&p_hpl,   g_hpl);
    cudaGetSymbolAddress((void**)&p_gi,    g_gi);
    cudaGetSymbolAddress((void**)&p_gh,    g_gh);
    cudaGetSymbolAddress((void**)&p_hpr,   g_hpr);
    cudaGetSymbolAddress((void**)&p_q2,    g_q2);
    cudaGetSymbolAddress((void**)&p_G3,    g_G3);
    cudaGetSymbolAddress((void**)&p_b3,    g_b3);
    cudaGetSymbolAddress((void**)&p_WcmbT, g_WcmbT);

    cudaFuncSetAttribute(gemm_tc<0,0>, cudaFuncAttributeMaxDynamicSharedMemorySize, GEMM_SMEM);
    cudaFuncSetAttribute(gemm_tc<1,0>, cudaFuncAttributeMaxDynamicSharedMemorySize, GEMM_SMEM);
    cudaFuncSetAttribute(gemm_tc<0,1>, cudaFuncAttributeMaxDynamicSharedMemorySize, GEMM_SMEM);
    cudaFuncSetAttribute(mha2_kernel, cudaFuncAttributeMaxDynamicSharedMemorySize, MHA2_SMEM);
    cudaFuncSetAttribute(attn2_kernel, cudaFuncAttributeMaxDynamicSharedMemorySize, ATT2_SMEM);
    cudaFuncSetAttribute(ode_kernel, cudaFuncAttributeMaxDynamicSharedMemorySize, ODE_SMEM);

    // --- prep ---
    prep_q<<<2, DM>>>(in_proj_w, in_proj_b, time_b, p_q2);
    prep_G<<<640, 256>>>(in_proj_w, in_proj_b, out_proj_w, out_proj_b,
                         outfn_w, outfn_b, attn_wq, attn_wv, merge_w,
                         p_G3, p_b3, p_WcmbT);
    bias_init<<<BS, NF>>>(p_b3, p_qh);   // qh <- b3 (split-K accumulates on top)

    // --- main pipeline ---
    mha2_kernel<<<BS, 256, MHA2_SMEM>>>(nids, hist_nids, anon, eids, hist_ts, dirs,
                                        node_feat, edge_feat, anony_emb, time_w, time_b,
                                        p_q2, p_wctx, p_last);
    // qh += wctx @ G3^T  (split-K=4: 4 slices of K=320, atomicAdd)
    gemm_tc<0,1><<<dim3(1, BS/128, 4), 256, GEMM_SMEM>>>(
        p_wctx, 2*DM, p_G3, 2*DM, nullptr, p_qh, NF, BS, NF, 320);
    // qh2 = qh @ attn_wk^T    (4096 x 384, K=128)
    gemm_tc<0,0><<<dim3(NB3/128, BS/128), 256, GEMM_SMEM>>>(
        p_qh, NF, attn_wk, NF, nullptr, p_qh2, NB3, BS, NB3, NF);
    attn2_kernel<<<BS, 128, ATT2_SMEM>>>(nids, hist_nids, eids, hist_ts,
                                         node_feat, edge_feat, time_w, time_b,
                                         p_qh2, p_A2);
    // hpl = tanh(A2 @ WcmbT^T + merge_b)   (4096 x 128, K=512)
    gemm_tc<1,0><<<dim3(1, BS/128), 256, GEMM_SMEM>>>(
        p_A2, 512, p_WcmbT, 512, merge_b, p_hpl, NF, BS, NF, 512);
    // gi = last @ gru_w_ih^T + b   (K=512)
    gemm_tc<0,0><<<dim3(3*NF/128, BS/128), 256, GEMM_SMEM>>>(
        p_last, DIN, gru_w_ih, DIN, gru_b_ih, p_gi, 3*NF, BS, 3*NF, DIN);
    // gh = hpl @ gru_w_hh^T + b    (K=128)
    gemm_tc<0,0><<<dim3(3*NF/128, BS/128), 256, GEMM_SMEM>>>(
        p_hpl, NF, gru_w_hh, NF, gru_b_hh, p_gh, 3*NF, BS, 3*NF, NF);
    gru_kernel<<<(BS*NF + 255)/256, 256>>>(p_gi, p_gh, p_hpl, p_hpr);
    ode_kernel<<<BS, 128, ODE_SMEM>>>(p_hpr, ode_w, ode_b, tnode_w, tnode_b, hist_ts, out);
}

// round 12
// speedup vs baseline: 1.1733x; 1.1733x over previous
#include <cuda_runtime.h>
#include <math.h>
#include <stdint.h>

#define BS   4096
#define L    20
#define NF   128
#define DM   640
#define DIN  512
#define DH   320
#define NB3  384

// ---------------- scratch ----------------
__device__ float g_last [BS*DIN];
__device__ float g_wctx [BS*2*DM];
__device__ float g_qh   [BS*NF];
__device__ float g_qh2  [BS*NB3];
__device__ float g_A2   [BS*512];
__device__ float g_hpl  [BS*NF];
__device__ float g_gi   [BS*3*NF];
__device__ float g_gh   [BS*3*NF];
__device__ float g_hpr  [BS*NF];
__device__ float g_q2   [2*DM];
__device__ float g_G3   [NF*2*DM];
__device__ float g_b3   [NF];
__device__ float g_WcmbT[NF*512];

__device__ __forceinline__ unsigned f2tf(float v) {
    unsigned r;
    asm("cvt.rna.tf32.f32 %0, %1;" : "=r"(r) : "f"(v));
    return r;
}
__device__ __forceinline__ uint32_t smem_u32(const void* p) {
    uint32_t a;
    asm("{ .reg .u64 t; cvta.to.shared.u64 t, %1; cvt.u32.u64 %0, t; }" : "=r"(a) : "l"(p));
    return a;
}
static __device__ __forceinline__ void cp16(uint32_t s, const void* g) {
    asm volatile("cp.async.cg.shared.global [%0], [%1], 16;" :: "r"(s), "l"(g));
}
__device__ __forceinline__ void mma_tf32(float c[4], unsigned a0, unsigned a1,
                                         unsigned a2, unsigned a3,
                                         unsigned b0, unsigned b1) {
    asm volatile(
        "mma.sync.aligned.m16n8k8.row.col.f32.tf32.tf32.f32 "
        "{%0,%1,%2,%3}, {%4,%5,%6,%7}, {%8,%9}, {%0,%1,%2,%3};"
        : "+f"(c[0]), "+f"(c[1]), "+f"(c[2]), "+f"(c[3])
        : "r"(a0), "r"(a1), "r"(a2), "r"(a3), "r"(b0), "r"(b1));
}

// ---------------- tf32 GEMM (round-9/10 proven core) ----------------
#define GS 3
#define STG_F (128*20)
#define GEMM_SMEM (GS*2*STG_F*4)

template<int ACT, int RED>
__global__ __launch_bounds__(256, 2) void gemm_tc(
    const float* __restrict__ A, int lda,
    const float* __restrict__ B, int ldb,
    const float* __restrict__ bias,
    float* __restrict__ C, int ldc,
    int M, int N, int K)
{
    extern __shared__ float smem[];
    const uint32_t smb = smem_u32(smem);
    const int bm = blockIdx.y * 128;
    const int bn = blockIdx.x * 128;
    const size_t kofs = (size_t)blockIdx.z * K;
    const int t  = threadIdx.x;
    const int lane = t & 31;
    const int wr = (t >> 5) >> 2;
    const int wc = (t >> 5) & 3;
    const int g = lane >> 2, tig = lane & 3;

    const int niter = K >> 4;
    const float* Abase = A + (size_t)bm * lda + kofs;
    const float* Bbase = B + (size_t)bn * ldb + kofs;

    auto load_stage = [&](int s, int c) {
        uint32_t as = smb + (uint32_t)(s * 2 * STG_F) * 4;
        uint32_t bs = as + STG_F * 4;
        const float* Ac = Abase + c * 16;
        const float* Bc = Bbase + c * 16;
        #pragma unroll
        for (int i = 0; i < 2; i++) {
            int id = i * 256 + t;
            int row = id >> 2, seg = id & 3;
            cp16(as + (uint32_t)(row * 20 + seg * 4) * 4, Ac + (size_t)row * lda + seg * 4);
            cp16(bs + (uint32_t)(row * 20 + seg * 4) * 4, Bc + (size_t)row * ldb + seg * 4);
        }
    };

    float acc[4][4][4] = {};

    #pragma unroll
    for (int s = 0; s < GS - 1; s++) {
        if (s < niter) load_stage(s, s);
        asm volatile("cp.async.commit_group;" ::: "memory");
    }

    for (int c = 0; c < niter; c++) {
        asm volatile("cp.async.wait_group %0;" :: "n"(GS - 2) : "memory");
        __syncthreads();
        if (c + GS - 1 < niter) load_stage((c + GS - 1) % GS, c + GS - 1);
        asm volatile("cp.async.commit_group;" ::: "memory");

        const float* As  = smem + (c % GS) * 2 * STG_F;
        const float* Bsm = As + STG_F;
        #pragma unroll
        for (int s8 = 0; s8 < 2; s8++) {
            const int kk = s8 * 8;
            unsigned af[4][4]; unsigned bf[4][2];
            #pragma unroll
            for (int i = 0; i < 4; i++) {
                int r0 = (wr * 64 + i * 16 + g) * 20 + kk + tig;
                af[i][0] = f2tf(As[r0]);
                af[i][1] = f2tf(As[r0 + 8 * 20]);
                af[i][2] = f2tf(As[r0 + 4]);
                af[i][3] = f2tf(As[r0 + 8 * 20 + 4]);
            }
            #pragma unroll
            for (int j = 0; j < 4; j++) {
                int n0 = (wc * 32 + j * 8 + g) * 20 + kk + tig;
                bf[j][0] = f2tf(Bsm[n0]);
                bf[j][1] = f2tf(Bsm[n0 + 4]);
            }
            #pragma unroll
            for (int i = 0; i < 4; i++)
                #pragma unroll
                for (int j = 0; j < 4; j++)
                    mma_tf32(acc[i][j], af[i][0], af[i][1], af[i][2], af[i][3],
                             bf[j][0], bf[j][1]);
        }
    }

    #pragma unroll
    for (int i = 0; i < 4; i++) {
        int row = bm + wr * 64 + i * 16 + g;
        #pragma unroll
        for (int j = 0; j < 4; j++) {
            int col = bn + wc * 32 + j * 8 + tig * 2;
            if (RED) {
                atomicAdd(C + (size_t)row * ldc + col,           acc[i][j][0]);
                atomicAdd(C + (size_t)row * ldc + col + 1,       acc[i][j][1]);
                atomicAdd(C + (size_t)(row + 8) * ldc + col,     acc[i][j][2]);
                atomicAdd(C + (size_t)(row + 8) * ldc + col + 1, acc[i][j][3]);
            } else {
                float b0 = bias ? bias[col] : 0.f;
                float b1 = bias ? bias[col + 1] : 0.f;
                float v00 = acc[i][j][0] + b0, v01 = acc[i][j][1] + b1;
                float v10 = acc[i][j][2] + b0, v11 = acc[i][j][3] + b1;
                if (ACT == 1) { v00 = tanhf(v00); v01 = tanhf(v01);
                                v10 = tanhf(v10); v11 = tanhf(v11); }
                *(float2*)(C + (size_t)row * ldc + col)       = make_float2(v00, v01);
                *(float2*)(C + (size_t)(row + 8) * ldc + col) = make_float2(v10, v11);
            }
        }
    }
}

__global__ void bias_init(const float* __restrict__ bias, float* __restrict__ C) {
    C[(size_t)blockIdx.x * NF + threadIdx.x] = bias[threadIdx.x];
}

// ---------------- prep_q ----------------
__global__ void prep_q(const float* __restrict__ ipw, const float* __restrict__ ipb,
                       const float* __restrict__ time_b, float* __restrict__ q2)
{
    __shared__ float tc[NF];
    __shared__ float q0s[DH];
    int h = blockIdx.x, t = threadIdx.x;
    if (t < NF) tc[t] = cosf(time_b[t]);
    __syncthreads();
    if (t < DH) {
        int e = h*DH + t;
        float acc = ipb[e];
        const float* row = ipw + (size_t)e * DM + DIN;
        for (int k = 0; k < NF; k++) acc += tc[k] * row[k];
        q0s[t] = acc;
    }
    __syncthreads();
    float acc = 0.f;
    const float* base = ipw + (size_t)(DM + h*DH) * DM + t;
    for (int d = 0; d < DH; d++) acc += q0s[d] * base[(size_t)d * DM];
    q2[h*DM + t] = acc;
}

// ---------------- prep_G ----------------
__global__ __launch_bounds__(256) void prep_G(
    const float* __restrict__ ipw, const float* __restrict__ ipb,
    const float* __restrict__ opw, const float* __restrict__ opb,
    const float* __restrict__ wf, const float* __restrict__ bf,
    const float* __restrict__ wq, const float* __restrict__ wv,
    const float* __restrict__ mw,
    float* __restrict__ G3, float* __restrict__ b3, float* __restrict__ WcmbT)
{
    int i = blockIdx.x, t = threadIdx.x;
    if (i >= 128) {
        int r = i - 128;
        if (r < 384) {
            if (t < NF) {
                float acc = 0.f;
                const float* wvr = wv + (size_t)r * NF;
                for (int k = 0; k < NF; k++) acc += wvr[k] * mw[k * NF + t];
                WcmbT[(size_t)t * 512 + r] = acc;
            }
        } else {
            int r2 = r - 384;
            if (t < NF) WcmbT[(size_t)t * 512 + 384 + r2] = mw[(NF + r2) * NF + t];
        }
        return;
    }
    __shared__ float wqc[NF];
    __shared__ float b1s[NF];
    __shared__ float t2[DM];
    __shared__ float gt[DM];
    __shared__ float red[256];
    if (t < NF) {
        wqc[t] = wq[t * NF + i];
        float acc = bf[t];
        const float* row = wf + (size_t)t * DM;
        for (int m = 0; m < DM; m++) acc += row[m] * opb[m];
        b1s[t] = acc;
    }
    __syncthreads();
    for (int j = t; j < DM; j += 256) {
        float acc = 0.f;
        for (int q = 0; q < NF; q++) acc += wqc[q] * wf[(size_t)q * DM + j];
        t2[j] = acc;
    }
    __syncthreads();
    for (int d = t; d < DM; d += 256) {
        float acc = 0.f;
        for (int m = 0; m < DM; m++) acc += t2[m] * opw[(size_t)m * DM + d];
        gt[d] = acc;
    }
    __syncthreads();
    for (int c = t; c < 2*DM; c += 256) {
        int h = c / DM, cc = c - h*DM;
        float acc = 0.f;
        const float* base = ipw + (size_t)(2*DM + h*DH) * DM + cc;
        const float* gth = gt + h*DH;
        for (int dd = 0; dd < DH; dd++) acc += gth[dd] * base[(size_t)dd * DM];
        G3[(size_t)i * (2*DM) + c] = acc;
    }
    float p = 0.f;
    for (int d = t; d < DM; d += 256) p += gt[d] * ipb[2*DM + d];
    if (t < NF) p += b1s[t] * wqc[t];
    red[t] = p;
    __syncthreads();
    if (t == 0) {
        float s = 0.f;
        for (int k = 0; k < 256; k++) s += red[k];
        b3[i] = s;
    }
}

// ---------------- MHA stage: vectorized gather + scores + weighted sums ----------------
// smem layout (floats): rows[L*DM] | q2s[2*DM] | sc[64] | tw[128] | tb[128] |
//                       dts[L] | (ptrs: 4*L float* 8B-aligned) | hn[L]
#define MHA2_SMEM ((L*DM + 2*DM + 64 + 256 + L) * 4 + 4*L*8 + L*4 + 16)
__global__ __launch_bounds__(256) void mha2_kernel(
    const int* __restrict__ nids, const int* __restrict__ hist_nids,
    const int* __restrict__ anon_ids, const int* __restrict__ hist_eids,
    const float* __restrict__ hist_ts, const int* __restrict__ hist_dirs,
    const float* __restrict__ node_feat, const float* __restrict__ edge_feat,
    const float* __restrict__ anony_emb, const float* __restrict__ time_w,
    const float* __restrict__ time_b, const float* __restrict__ q2,
    float* __restrict__ wctx, float* __restrict__ last)
{
    extern __shared__ float sm[];
    float* rows = sm;                          // [L][640]
    float* q2s  = rows + L*DM;                 // [1280]
    float* sc   = q2s + 2*DM;                  // [64]
    float* tw   = sc + 64;                     // [128]
    float* tb   = tw + 128;                    // [128]
    float* dts  = tb + 128;                    // [20]
    const float** ptrs = (const float**)(((uintptr_t)(dts + L) + 15) & ~(uintptr_t)15); // [4][L]
    int*   hn   = (int*)(ptrs + 4*L);          // [20]

    int b = blockIdx.x, t = threadIdx.x;
    int w = t >> 5, lane = t & 31;

    if (t < 128) { tw[t] = time_w[t]; tb[t] = time_b[t]; }
    if (t < L) {
        int hn_  = hist_nids[b*L + t];
        int eid_ = hist_eids[b*L + t];
        int aid_ = anon_ids[b*L + t];
        int dir_ = hist_dirs[b*L + t];
        int nid  = nids[b];
        hn[t]  = hn_;
        dts[t] = hist_ts[b*L + L-1] - hist_ts[b*L + t];
        ptrs[0*L + t] = node_feat + (size_t)(dir_ ? nid : hn_) * NF;
        ptrs[1*L + t] = node_feat + (size_t)(dir_ ? hn_ : nid) * NF;
        ptrs[2*L + t] = anony_emb + (size_t)aid_ * NF;
        ptrs[3*L + t] = edge_feat + (size_t)eid_ * NF;
    }
    for (int i = t; i < 2*DM; i += 256)
        ((float*)q2s)[i] = q2[i];              // scalar fine (small)
    __syncthreads();

    // gather: 100 (m,seg) row-tasks, warp-per-task, one float4 per lane
    for (int task = w; task < 5*L; task += 8) {
        int seg = task / L, m = task - seg*L;  // warp-uniform
        float4 v;
        if (seg < 4) {
            v = *(const float4*)(ptrs[seg*L + m] + lane*4);
            if (m == L-1) {
                *(float4*)(last + (size_t)b*DIN + seg*128 + lane*4) = v;
                v = make_float4(0.f, 0.f, 0.f, 0.f);
            }
        } else {
            float d = dts[m];
            float4 w4 = *(const float4*)(tw + lane*4);
            float4 b4 = *(const float4*)(tb + lane*4);
            v.x = cosf(fmaf(d, w4.x, b4.x));
            v.y = cosf(fmaf(d, w4.y, b4.y));
            v.z = cosf(fmaf(d, w4.z, b4.z));
            v.w = cosf(fmaf(d, w4.w, b4.w));
        }
        *(float4*)(rows + m*DM + seg*128 + lane*4) = v;
    }
    __syncthreads();

    // scores: 40 (h,m) dots over 640, warp-per-dot, float4
    const float4* rows4 = (const float4*)rows;
    const float4* q2s4  = (const float4*)q2s;
    for (int p = w; p < 2*L; p += 8) {
        int h = p / L, m = p - h*L;
        const float4* qp = q2s4 + h*160;
        const float4* rp = rows4 + m*160;
        float s = 0.f;
        #pragma unroll
        for (int k = 0; k < 5; k++) {
            float4 a = qp[lane + k*32];
            float4 r = rp[lane + k*32];
            s += a.x*r.x + a.y*r.y + a.z*r.z + a.w*r.w;
        }
        #pragma unroll
        for (int o = 16; o; o >>= 1) s += __shfl_xor_sync(0xffffffffu, s, o);
        if (lane == 0) {
            bool msk = (hn[m] == 0) && (m != L-1);
            sc[p] = msk ? -1e9f : s * (1.f / sqrtf((float)DH));
        }
    }
    __syncthreads();
    if (t < 2) {
        float mx = -1e30f;
        for (int m = 0; m < L; m++) mx = fmaxf(mx, sc[t*L + m]);
        float sum = 0.f;
        for (int m = 0; m < L; m++) { float e = expf(sc[t*L + m] - mx); sc[t*L + m] = e; sum += e; }
        float inv = 1.f / sum;
        for (int m = 0; m < L; m++) sc[t*L + m] *= inv;
    }
    __syncthreads();

    // weighted sums: 320 float4 outputs
    float4* wctx4 = (float4*)(wctx + (size_t)b*(2*DM));
    for (int i4 = t; i4 < 320; i4 += 256) {
        int h = i4 / 160, d4 = i4 - h*160;
        float4 acc = make_float4(0.f, 0.f, 0.f, 0.f);
        const float* scp = sc + h*L;
        #pragma unroll
        for (int m = 0; m < L; m++) {
            float a = scp[m];
            float4 r = rows4[m*160 + d4];
            acc.x += a*r.x; acc.y += a*r.y; acc.z += a*r.z; acc.w += a*r.w;
        }
        wctx4[i4] = acc;
    }
}

// ---------------- pooling attention stage: vectorized ----------------
#define ATT2_SMEM ((L*NB3 + NB3 + 32 + 256 + L) * 4 + 2*L*8 + L*4 + 16)
__global__ __launch_bounds__(128) void attn2_kernel(
    const int* __restrict__ nids, const int* __restrict__ hist_nids,
    const int* __restrict__ hist_eids, const float* __restrict__ hist_ts,
    const float* __restrict__ node_feat, const float* __restrict__ edge_feat,
    const float* __restrict__ time_w, const float* __restrict__ time_b,
    const float* __restrict__ qh2,
    float* __restrict__ A2)
{
    extern __shared__ float sm[];
    float* rows = sm;                          // [L][384]
    float* qs   = rows + L*NB3;                // [384]
    float* a    = qs + NB3;                    // [32]
    float* tw   = a + 32;                      // [128]
    float* tb   = tw + 128;                    // [128]
    float* dts  = tb + 128;                    // [20]
    const float** ptrs = (const float**)(((uintptr_t)(dts + L) + 15) & ~(uintptr_t)15); // [2][L]
    int*   hn   = (int*)(ptrs + 2*L);

    int b = blockIdx.x, t = threadIdx.x;
    int w = t >> 5, lane = t & 31;

    if (t < 128) { tw[t] = time_w[t]; tb[t] = time_b[t]; }
    if (t < L) {
        int hn_  = hist_nids[b*L + t];
        int eid_ = hist_eids[b*L + t];
        hn[t]  = hn_;
        dts[t] = hist_ts[b*L + L-1] - hist_ts[b*L + t];
        ptrs[0*L + t] = node_feat + (size_t)hn_ * NF;
        ptrs[1*L + t] = edge_feat + (size_t)eid_ * NF;
    }
    {   // qs load, float4
        float4* qs4 = (float4*)qs;
        const float4* src = (const float4*)(qh2 + (size_t)b*NB3);
        if (t < 96) qs4[t] = src[t];
    }
    __syncthreads();

    // gather: 60 (m,seg) row-tasks over 4 warps
    for (int task = w; task < 3*L; task += 4) {
        int seg = task / L, m = task - seg*L;
        float4 v;
        if (seg < 2) {
            v = *(const float4*)(ptrs[seg*L + m] + lane*4);
        } else {
            float d = dts[m];
            float4 w4 = *(const float4*)(tw + lane*4);
            float4 b4 = *(const float4*)(tb + lane*4);
            v.x = cosf(fmaf(d, w4.x, b4.x));
            v.y = cosf(fmaf(d, w4.y, b4.y));
            v.z = cosf(fmaf(d, w4.z, b4.z));
            v.w = cosf(fmaf(d, w4.w, b4.w));
        }
        *(float4*)(rows + m*NB3 + seg*128 + lane*4) = v;
    }
    __syncthreads();

    const float4* rows4 = (const float4*)rows;
    const float4* qs4   = (const float4*)qs;
    for (int l = w; l < L; l += 4) {
        const float4* rp = rows4 + l*96;
        float s = 0.f;
        #pragma unroll
        for (int k = 0; k < 3; k++) {
            float4 q = qs4[lane + k*32];
            float4 r = rp[lane + k*32];
            s += q.x*r.x + q.y*r.y + q.z*r.z + q.w*r.w;
        }
        #pragma unroll
        for (int o = 16; o; o >>= 1) s += __shfl_xor_sync(0xffffffffu, s, o);
        if (lane == 0) {
            bool msk = (hn[l] == 0) && (l != L-1);
            a[l] = msk ? -1e9f : s * (1.f / sqrtf((float)NF));
        }
    }
    __syncthreads();
    if (t == 0) {
        float mx = -1e30f;
        for (int l = 0; l < L; l++) mx = fmaxf(mx, a[l]);
        float sum = 0.f;
        for (int l = 0; l < L; l++) { float e = expf(a[l] - mx); a[l] = e; sum += e; }
        float inv = 1.f / sum;
        for (int l = 0; l < L; l++) a[l] *= inv;
    }
    __syncthreads();

    float4* A24 = (float4*)(A2 + (size_t)b*512);
    if (t < 96) {
        float4 acc = make_float4(0.f, 0.f, 0.f, 0.f);
        #pragma unroll
        for (int l = 0; l < L; l++) {
            float al = a[l];
            float4 r = rows4[l*96 + t];
            acc.x += al*r.x; acc.y += al*r.y; acc.z += al*r.z; acc.w += al*r.w;
        }
        A24[t] = acc;
    }
    if (t < 32) {
        const float4* nf4 = (const float4*)(node_feat + (size_t)nids[b]*NF);
        A24[96 + t] = nf4[t];
    }
}

// ---------------- GRU ----------------
__global__ void gru_kernel(const float* __restrict__ gi, const float* __restrict__ gh,
                           const float* __restrict__ hpl, float* __restrict__ hpr)
{
    int idx = blockIdx.x * blockDim.x + threadIdx.x;
    if (idx >= BS*NF) return;
    int b = idx / NF, f = idx - b*NF;
    const float* gib = gi + (size_t)b*3*NF;
    const float* ghb = gh + (size_t)b*3*NF;
    float r = 1.f / (1.f + expf(-(gib[f]      + ghb[f])));
    float z = 1.f / (1.f + expf(-(gib[NF + f] + ghb[NF + f])));
    float n = tanhf(gib[2*NF + f] + r * ghb[2*NF + f]);
    hpr[idx] = (1.f - z) * n + z * hpl[idx];
}

// ---------------- RK4 ODE (round-10) ----------------
#define ODE_SMEM ((128*129 + 2*128) * 4)
__global__ __launch_bounds__(128) void ode_kernel(
    const float* __restrict__ hpr, const float* __restrict__ ode_w,
    const float* __restrict__ ode_b, const float* __restrict__ tnode_w,
    const float* __restrict__ tnode_b, const float* __restrict__ hist_ts,
    float* __restrict__ out)
{
    extern __shared__ float sm[];
    float* Wsm = sm;
    float* vs  = sm + 128*129;
    int b = blockIdx.x, f = threadIdx.x;
    for (int i = f; i < NF*NF; i += 128) Wsm[(i >> 7)*129 + (i & 127)] = ode_w[i];
    float t0 = hist_ts[b*L + L-2];
    float t1 = hist_ts[b*L + L-1];
    float ratio = t1 - t0;
    float twf = tnode_w[f], tbf = tnode_b[f], obf = ode_b[f];
    float h0 = hpr[(size_t)b*NF + f];
    float z = h0;
    __syncthreads();
    float w[NF];
    #pragma unroll
    for (int k = 0; k < NF; k++) w[k] = Wsm[f*129 + k];
    __syncthreads();

    int buf = 0;
    auto feval = [&](float s, float zin) -> float {
        float* vb = vs + buf * 128;
        float t = fmaf(s, ratio, t0);
        vb[f] = zin + cosf(fmaf(t, twf, tbf));
        __syncthreads();
        float a0 = 0.f, a1 = 0.f, a2 = 0.f, a3 = 0.f;
        #pragma unroll
        for (int k = 0; k < NF; k += 16) {
            float4 v0 = *(const float4*)&vb[k];
            float4 v1 = *(const float4*)&vb[k+4];
            float4 v2 = *(const float4*)&vb[k+8];
            float4 v3 = *(const float4*)&vb[k+12];
            a0 += v0.x*w[k]    + v0.y*w[k+1]  + v0.z*w[k+2]  + v0.w*w[k+3];
            a1 += v1.x*w[k+4]  + v1.y*w[k+5]  + v1.z*w[k+6]  + v1.w*w[k+7];
            a2 += v2.x*w[k+8]  + v2.y*w[k+9]  + v2.z*w[k+10] + v2.w*w[k+11];
            a3 += v3.x*w[k+12] + v3.y*w[k+13] + v3.z*w[k+14] + v3.w*w[k+15];
        }
        buf ^= 1;
        return tanhf(obf + ((a0 + a1) + (a2 + a3))) * ratio;
    };

    const float ds = 0.125f;
    for (int st = 0; st < 8; st++) {
        float s = st * ds;
        float k1 = feval(s,            z);
        float k2 = feval(s + 0.5f*ds,  z + 0.5f*ds*k1);
        float k3 = feval(s + 0.5f*ds,  z + 0.5f*ds*k2);
        float k4 = feval(s + ds,       z + ds*k3);
        z += ds * (1.f/6.f) * (k1 + 2.f*k2 + 2.f*k3 + k4);
    }
    out[(size_t)b*NF + f] = z;
    out[(size_t)BS*NF + (size_t)b*NF + f] = h0;
    if (f == 0) out[(size_t)2*BS*NF + b] = t1;
}

// ---------------- launch ----------------
extern "C" void kernel_launch(void* const* d_in, const int* in_sizes, int n_in,
                              void* d_out, int out_size)
{
    const int*   nids      = (const int*)  d_in[0];
    const int*   hist_nids = (const int*)  d_in[2];
    const int*   anon      = (const int*)  d_in[3];
    const int*   eids      = (const int*)  d_in[4];
    const float* hist_ts   = (const float*)d_in[5];
    const int*   dirs      = (const int*)  d_in[6];
    const float* node_feat = (const float*)d_in[7];
    const float* edge_feat = (const float*)d_in[8];
    const float* anony_emb = (const float*)d_in[9];
    const float* time_w    = (const float*)d_in[10];
    const float* time_b    = (const float*)d_in[11];
    const float* in_proj_w = (const float*)d_in[12];
    const float* in_proj_b = (const float*)d_in[13];
    const float* out_proj_w= (const float*)d_in[14];
    const float* out_proj_b= (const float*)d_in[15];
    const float* outfn_w   = (const float*)d_in[16];
    const float* outfn_b   = (const float*)d_in[17];
    const float* attn_wq   = (const float*)d_in[18];
    const float* attn_wk   = (const float*)d_in[19];
    const float* attn_wv   = (const float*)d_in[20];
    const float* merge_w   = (const float*)d_in[21];
    const float* merge_b   = (const float*)d_in[22];
    const float* gru_w_ih  = (const float*)d_in[23];
    const float* gru_w_hh  = (const float*)d_in[24];
    const float* gru_b_ih  = (const float*)d_in[25];
    const float* gru_b_hh  = (const float*)d_in[26];
    const float* ode_w     = (const float*)d_in[27];
    const float* ode_b     = (const float*)d_in[28];
    const float* tnode_w   = (const float*)d_in[29];
    const float* tnode_b   = (const float*)d_in[30];
    float* out = (float*)d_out;

    float *p_last, *p_wctx, *p_qh, *p_qh2, *p_A2, *p_hpl, *p_gi, *p_gh, *p_hpr,
          *p_q2, *p_G3, *p_b3, *p_WcmbT;
    cudaGetSymbolAddress((void**)&p_last,  g_last);
    cudaGetSymbolAddress((void**)&p_wctx,  g_wctx);
    cudaGetSymbolAddress((void**)&p_qh,    g_qh);
    cudaGetSymbolAddress((void**)&p_qh2,   g_qh2);
    cudaGetSymbolAddress((void**)&p_A2,    g_A2);
    cudaGetSymbolAddress((void**)&p_hpl,   g_hpl);
    cudaGetSymbolAddress((void**)&p_gi,    g_gi);
    cudaGetSymbolAddress((void**)&p_gh,    g_gh);
    cudaGetSymbolAddress((void**)&p_hpr,   g_hpr);
    cudaGetSymbolAddress((void**)&p_q2,    g_q2);
    cudaGetSymbolAddress((void**)&p_G3,    g_G3);
    cudaGetSymbolAddress((void**)&p_b3,    g_b3);
    cudaGetSymbolAddress((void**)&p_WcmbT, g_WcmbT);

    cudaFuncSetAttribute(gemm_tc<0,0>, cudaFuncAttributeMaxDynamicSharedMemorySize, GEMM_SMEM);
    cudaFuncSetAttribute(gemm_tc<1,0>, cudaFuncAttributeMaxDynamicSharedMemorySize, GEMM_SMEM);
    cudaFuncSetAttribute(gemm_tc<0,1>, cudaFuncAttributeMaxDynamicSharedMemorySize, GEMM_SMEM);
    cudaFuncSetAttribute(mha2_kernel, cudaFuncAttributeMaxDynamicSharedMemorySize, MHA2_SMEM);
    cudaFuncSetAttribute(attn2_kernel, cudaFuncAttributeMaxDynamicSharedMemorySize, ATT2_SMEM);
    cudaFuncSetAttribute(ode_kernel, cudaFuncAttributeMaxDynamicSharedMemorySize, ODE_SMEM);

    // --- prep ---
    prep_q<<<2, DM>>>(in_proj_w, in_proj_b, time_b, p_q2);
    prep_G<<<640, 256>>>(in_proj_w, in_proj_b, out_proj_w, out_proj_b,
                         outfn_w, outfn_b, attn_wq, attn_wv, merge_w,
                         p_G3, p_b3, p_WcmbT);
    bias_init<<<BS, NF>>>(p_b3, p_qh);

    // --- main pipeline ---
    mha2_kernel<<<BS, 256, MHA2_SMEM>>>(nids, hist_nids, anon, eids, hist_ts, dirs,
                                        node_feat, edge_feat, anony_emb, time_w, time_b,
                                        p_q2, p_wctx, p_last);
    gemm_tc<0,1><<<dim3(1, BS/128, 4), 256, GEMM_SMEM>>>(
        p_wctx, 2*DM, p_G3, 2*DM, nullptr, p_qh, NF, BS, NF, 320);
    gemm_tc<0,0><<<dim3(NB3/128, BS/128), 256, GEMM_SMEM>>>(
        p_qh, NF, attn_wk, NF, nullptr, p_qh2, NB3, BS, NB3, NF);
    attn2_kernel<<<BS, 128, ATT2_SMEM>>>(nids, hist_nids, eids, hist_ts,
                                         node_feat, edge_feat, time_w, time_b,
                                         p_qh2, p_A2);
    gemm_tc<1,0><<<dim3(1, BS/128), 256, GEMM_SMEM>>>(
        p_A2, 512, p_WcmbT, 512, merge_b, p_hpl, NF, BS, NF, 512);
    gemm_tc<0,0><<<dim3(3*NF/128, BS/128), 256, GEMM_SMEM>>>(
        p_last, DIN, gru_w_ih, DIN, gru_b_ih, p_gi, 3*NF, BS, 3*NF, DIN);
    gemm_tc<0,0><<<dim3(3*NF/128, BS/128), 256, GEMM_SMEM>>>(
        p_hpl, NF, gru_w_hh, NF, gru_b_hh, p_gh, 3*NF, BS, 3*NF, NF);
    gru_kernel<<<(BS*NF + 255)/256, 256>>>(p_gi, p_gh, p_hpl, p_hpr);
    ode_kernel<<<BS, 128, ODE_SMEM>>>(p_hpr, ode_w, ode_b, tnode_w, tnode_b, hist_ts, out);
}

// round 13
// speedup vs baseline: 1.3285x; 1.1323x over previous
#include <cuda_runtime.h>
#include <math.h>
#include <stdint.h>

#define BS   4096
#define L    20
#define NF   128
#define DM   640
#define DIN  512
#define DH   320
#define NB3  384

// ---------------- scratch ----------------
__device__ float g_last [BS*DIN];
__device__ float g_wctx [BS*2*DM];
__device__ float g_qh   [BS*NF];
__device__ float g_qh2  [BS*NB3];
__device__ float g_A2   [BS*512];
__device__ float g_hpl  [BS*NF];
__device__ float g_gi   [BS*3*NF];
__device__ float g_gh   [BS*3*NF];
__device__ float g_hpr  [BS*NF];
__device__ float g_q2   [2*DM];
__device__ float g_G3   [NF*2*DM];
__device__ float g_b3   [NF];
__device__ float g_WcmbT[NF*512];

__device__ __forceinline__ unsigned f2tf(float v) {
    unsigned r;
    asm("cvt.rna.tf32.f32 %0, %1;" : "=r"(r) : "f"(v));
    return r;
}
__device__ __forceinline__ uint32_t smem_u32(const void* p) {
    uint32_t a;
    asm("{ .reg .u64 t; cvta.to.shared.u64 t, %1; cvt.u32.u64 %0, t; }" : "=r"(a) : "l"(p));
    return a;
}
static __device__ __forceinline__ void cp16(uint32_t s, const void* g) {
    asm volatile("cp.async.cg.shared.global [%0], [%1], 16;" :: "r"(s), "l"(g));
}
__device__ __forceinline__ void mma_tf32(float c[4], unsigned a0, unsigned a1,
                                         unsigned a2, unsigned a3,
                                         unsigned b0, unsigned b1) {
    asm volatile(
        "mma.sync.aligned.m16n8k8.row.col.f32.tf32.tf32.f32 "
        "{%0,%1,%2,%3}, {%4,%5,%6,%7}, {%8,%9}, {%0,%1,%2,%3};"
        : "+f"(c[0]), "+f"(c[1]), "+f"(c[2]), "+f"(c[3])
        : "r"(a0), "r"(a1), "r"(a2), "r"(a3), "r"(b0), "r"(b1));
}
// packed f32x2 FMA (PTX 8.6, sm_100+; NOT an 'a'-only feature)
__device__ __forceinline__ void ffma2(unsigned long long& d, unsigned long long a,
                                      unsigned long long b) {
    asm("fma.rn.f32x2 %0, %1, %2, %0;" : "+l"(d) : "l"(a), "l"(b));
}
__device__ __forceinline__ unsigned long long packf2(float lo, float hi) {
    unsigned long long r;
    asm("mov.b64 %0, {%1, %2};" : "=l"(r) : "f"(lo), "f"(hi));
    return r;
}
__device__ __forceinline__ void unpackf2(float& lo, float& hi, unsigned long long v) {
    asm("mov.b64 {%0, %1}, %2;" : "=f"(lo), "=f"(hi) : "l"(v));
}

// ---------------- tf32 GEMM (proven core) ----------------
#define GS 3
#define STG_F (128*20)
#define GEMM_SMEM (GS*2*STG_F*4)

template<int ACT, int RED>
__global__ __launch_bounds__(256, 2) void gemm_tc(
    const float* __restrict__ A, int lda,
    const float* __restrict__ B, int ldb,
    const float* __restrict__ bias,
    float* __restrict__ C, int ldc,
    int M, int N, int K)
{
    extern __shared__ float smem[];
    const uint32_t smb = smem_u32(smem);
    const int bm = blockIdx.y * 128;
    const int bn = blockIdx.x * 128;
    const size_t kofs = (size_t)blockIdx.z * K;
    const int t  = threadIdx.x;
    const int lane = t & 31;
    const int wr = (t >> 5) >> 2;
    const int wc = (t >> 5) & 3;
    const int g = lane >> 2, tig = lane & 3;

    const int niter = K >> 4;
    const float* Abase = A + (size_t)bm * lda + kofs;
    const float* Bbase = B + (size_t)bn * ldb + kofs;

    auto load_stage = [&](int s, int c) {
        uint32_t as = smb + (uint32_t)(s * 2 * STG_F) * 4;
        uint32_t bs = as + STG_F * 4;
        const float* Ac = Abase + c * 16;
        const float* Bc = Bbase + c * 16;
        #pragma unroll
        for (int i = 0; i < 2; i++) {
            int id = i * 256 + t;
            int row = id >> 2, seg = id & 3;
            cp16(as + (uint32_t)(row * 20 + seg * 4) * 4, Ac + (size_t)row * lda + seg * 4);
            cp16(bs + (uint32_t)(row * 20 + seg * 4) * 4, Bc + (size_t)row * ldb + seg * 4);
        }
    };

    float acc[4][4][4] = {};

    #pragma unroll
    for (int s = 0; s < GS - 1; s++) {
        if (s < niter) load_stage(s, s);
        asm volatile("cp.async.commit_group;" ::: "memory");
    }

    for (int c = 0; c < niter; c++) {
        asm volatile("cp.async.wait_group %0;" :: "n"(GS - 2) : "memory");
        __syncthreads();
        if (c + GS - 1 < niter) load_stage((c + GS - 1) % GS, c + GS - 1);
        asm volatile("cp.async.commit_group;" ::: "memory");

        const float* As  = smem + (c % GS) * 2 * STG_F;
        const float* Bsm = As + STG_F;
        #pragma unroll
        for (int s8 = 0; s8 < 2; s8++) {
            const int kk = s8 * 8;
            unsigned af[4][4]; unsigned bf[4][2];
            #pragma unroll
            for (int i = 0; i < 4; i++) {
                int r0 = (wr * 64 + i * 16 + g) * 20 + kk + tig;
                af[i][0] = f2tf(As[r0]);
                af[i][1] = f2tf(As[r0 + 8 * 20]);
                af[i][2] = f2tf(As[r0 + 4]);
                af[i][3] = f2tf(As[r0 + 8 * 20 + 4]);
            }
            #pragma unroll
            for (int j = 0; j < 4; j++) {
                int n0 = (wc * 32 + j * 8 + g) * 20 + kk + tig;
                bf[j][0] = f2tf(Bsm[n0]);
                bf[j][1] = f2tf(Bsm[n0 + 4]);
            }
            #pragma unroll
            for (int i = 0; i < 4; i++)
                #pragma unroll
                for (int j = 0; j < 4; j++)
                    mma_tf32(acc[i][j], af[i][0], af[i][1], af[i][2], af[i][3],
                             bf[j][0], bf[j][1]);
        }
    }

    #pragma unroll
    for (int i = 0; i < 4; i++) {
        int row = bm + wr * 64 + i * 16 + g;
        #pragma unroll
        for (int j = 0; j < 4; j++) {
            int col = bn + wc * 32 + j * 8 + tig * 2;
            if (RED) {
                atomicAdd(C + (size_t)row * ldc + col,           acc[i][j][0]);
                atomicAdd(C + (size_t)row * ldc + col + 1,       acc[i][j][1]);
                atomicAdd(C + (size_t)(row + 8) * ldc + col,     acc[i][j][2]);
                atomicAdd(C + (size_t)(row + 8) * ldc + col + 1, acc[i][j][3]);
            } else {
                float b0 = bias ? bias[col] : 0.f;
                float b1 = bias ? bias[col + 1] : 0.f;
                float v00 = acc[i][j][0] + b0, v01 = acc[i][j][1] + b1;
                float v10 = acc[i][j][2] + b0, v11 = acc[i][j][3] + b1;
                if (ACT == 1) { v00 = tanhf(v00); v01 = tanhf(v01);
                                v10 = tanhf(v10); v11 = tanhf(v11); }
                *(float2*)(C + (size_t)row * ldc + col)       = make_float2(v00, v01);
                *(float2*)(C + (size_t)(row + 8) * ldc + col) = make_float2(v10, v11);
            }
        }
    }
}

__global__ void bias_init(const float* __restrict__ bias, float* __restrict__ C) {
    C[(size_t)blockIdx.x * NF + threadIdx.x] = bias[threadIdx.x];
}

// ---------------- prep_q ----------------
__global__ void prep_q(const float* __restrict__ ipw, const float* __restrict__ ipb,
                       const float* __restrict__ time_b, float* __restrict__ q2)
{
    __shared__ float tc[NF];
    __shared__ float q0s[DH];
    int h = blockIdx.x, t = threadIdx.x;
    if (t < NF) tc[t] = cosf(time_b[t]);
    __syncthreads();
    if (t < DH) {
        int e = h*DH + t;
        float acc = ipb[e];
        const float* row = ipw + (size_t)e * DM + DIN;
        for (int k = 0; k < NF; k++) acc += tc[k] * row[k];
        q0s[t] = acc;
    }
    __syncthreads();
    float acc = 0.f;
    const float* base = ipw + (size_t)(DM + h*DH) * DM + t;
    for (int d = 0; d < DH; d++) acc += q0s[d] * base[(size_t)d * DM];
    q2[h*DM + t] = acc;
}

// ---------------- prep_G ----------------
__global__ __launch_bounds__(256) void prep_G(
    const float* __restrict__ ipw, const float* __restrict__ ipb,
    const float* __restrict__ opw, const float* __restrict__ opb,
    const float* __restrict__ wf, const float* __restrict__ bf,
    const float* __restrict__ wq, const float* __restrict__ wv,
    const float* __restrict__ mw,
    float* __restrict__ G3, float* __restrict__ b3, float* __restrict__ WcmbT)
{
    int i = blockIdx.x, t = threadIdx.x;
    if (i >= 128) {
        int r = i - 128;
        if (r < 384) {
            if (t < NF) {
                float acc = 0.f;
                const float* wvr = wv + (size_t)r * NF;
                for (int k = 0; k < NF; k++) acc += wvr[k] * mw[k * NF + t];
                WcmbT[(size_t)t * 512 + r] = acc;
            }
        } else {
            int r2 = r - 384;
            if (t < NF) WcmbT[(size_t)t * 512 + 384 + r2] = mw[(NF + r2) * NF + t];
        }
        return;
    }
    __shared__ float wqc[NF];
    __shared__ float b1s[NF];
    __shared__ float t2[DM];
    __shared__ float gt[DM];
    __shared__ float red[256];
    if (t < NF) {
        wqc[t] = wq[t * NF + i];
        float acc = bf[t];
        const float* row = wf + (size_t)t * DM;
        for (int m = 0; m < DM; m++) acc += row[m] * opb[m];
        b1s[t] = acc;
    }
    __syncthreads();
    for (int j = t; j < DM; j += 256) {
        float acc = 0.f;
        for (int q = 0; q < NF; q++) acc += wqc[q] * wf[(size_t)q * DM + j];
        t2[j] = acc;
    }
    __syncthreads();
    for (int d = t; d < DM; d += 256) {
        float acc = 0.f;
        for (int m = 0; m < DM; m++) acc += t2[m] * opw[(size_t)m * DM + d];
        gt[d] = acc;
    }
    __syncthreads();
    for (int c = t; c < 2*DM; c += 256) {
        int h = c / DM, cc = c - h*DM;
        float acc = 0.f;
        const float* base = ipw + (size_t)(2*DM + h*DH) * DM + cc;
        const float* gth = gt + h*DH;
        for (int dd = 0; dd < DH; dd++) acc += gth[dd] * base[(size_t)dd * DM];
        G3[(size_t)i * (2*DM) + c] = acc;
    }
    float p = 0.f;
    for (int d = t; d < DM; d += 256) p += gt[d] * ipb[2*DM + d];
    if (t < NF) p += b1s[t] * wqc[t];
    red[t] = p;
    __syncthreads();
    if (t == 0) {
        float s = 0.f;
        for (int k = 0; k < 256; k++) s += red[k];
        b3[i] = s;
    }
}

// ---------------- MHA stage: cp.async gather + vectorized math ----------------
#define MHA2_SMEM ((L*DM + 2*DM + 64 + 256 + L) * 4 + 4*L*8 + L*4 + 16)
__global__ __launch_bounds__(256) void mha2_kernel(
    const int* __restrict__ nids, const int* __restrict__ hist_nids,
    const int* __restrict__ anon_ids, const int* __restrict__ hist_eids,
    const float* __restrict__ hist_ts, const int* __restrict__ hist_dirs,
    const float* __restrict__ node_feat, const float* __restrict__ edge_feat,
    const float* __restrict__ anony_emb, const float* __restrict__ time_w,
    const float* __restrict__ time_b, const float* __restrict__ q2,
    float* __restrict__ wctx, float* __restrict__ last)
{
    extern __shared__ float sm[];
    float* rows = sm;                          // [L][640]
    float* q2s  = rows + L*DM;                 // [1280]
    float* sc   = q2s + 2*DM;                  // [64]
    float* tw   = sc + 64;                     // [128]
    float* tb   = tw + 128;                    // [128]
    float* dts  = tb + 128;                    // [20]
    const float** ptrs = (const float**)(((uintptr_t)(dts + L) + 15) & ~(uintptr_t)15);
    int*   hn   = (int*)(ptrs + 4*L);

    int b = blockIdx.x, t = threadIdx.x;
    int w = t >> 5, lane = t & 31;
    const uint32_t rows_u = smem_u32(rows);

    if (t < 128) { tw[t] = time_w[t]; tb[t] = time_b[t]; }
    if (t < L) {
        int hn_  = hist_nids[b*L + t];
        int eid_ = hist_eids[b*L + t];
        int aid_ = anon_ids[b*L + t];
        int dir_ = hist_dirs[b*L + t];
        int nid  = nids[b];
        hn[t]  = hn_;
        dts[t] = hist_ts[b*L + L-1] - hist_ts[b*L + t];
        ptrs[0*L + t] = node_feat + (size_t)(dir_ ? nid : hn_) * NF;
        ptrs[1*L + t] = node_feat + (size_t)(dir_ ? hn_ : nid) * NF;
        ptrs[2*L + t] = anony_emb + (size_t)aid_ * NF;
        ptrs[3*L + t] = edge_feat + (size_t)eid_ * NF;
    }
    for (int i = t; i < 2*DM; i += 256) q2s[i] = q2[i];
    __syncthreads();

    // gather: seg<4 via cp.async (all in flight); seg==4 = cos compute
    for (int task = w; task < 5*L; task += 8) {
        int seg = task / L, m = task - seg*L;
        if (seg < 4) {
            cp16(rows_u + (uint32_t)(m*DM + seg*128 + lane*4) * 4,
                 ptrs[seg*L + m] + lane*4);
        } else {
            float d = dts[m];
            float4 w4 = *(const float4*)(tw + lane*4);
            float4 b4 = *(const float4*)(tb + lane*4);
            float4 v;
            v.x = cosf(fmaf(d, w4.x, b4.x));
            v.y = cosf(fmaf(d, w4.y, b4.y));
            v.z = cosf(fmaf(d, w4.z, b4.z));
            v.w = cosf(fmaf(d, w4.w, b4.w));
            *(float4*)(rows + m*DM + seg*128 + lane*4) = v;
        }
    }
    asm volatile("cp.async.commit_group;" ::: "memory");
    asm volatile("cp.async.wait_group 0;" ::: "memory");
    __syncthreads();

    // extract last-event features and zero them in rows
    if (t < 128) {
        float4 v = *(float4*)&rows[(L-1)*DM + t*4];
        *(float4*)(last + (size_t)b*DIN + t*4) = v;
        *(float4*)&rows[(L-1)*DM + t*4] = make_float4(0.f, 0.f, 0.f, 0.f);
    }
    __syncthreads();

    // scores
    const float4* rows4 = (const float4*)rows;
    const float4* q2s4  = (const float4*)q2s;
    for (int p = w; p < 2*L; p += 8) {
        int h = p / L, m = p - h*L;
        const float4* qp = q2s4 + h*160;
        const float4* rp = rows4 + m*160;
        float s = 0.f;
        #pragma unroll
        for (int k = 0; k < 5; k++) {
            float4 a = qp[lane + k*32];
            float4 r = rp[lane + k*32];
            s += a.x*r.x + a.y*r.y + a.z*r.z + a.w*r.w;
        }
        #pragma unroll
        for (int o = 16; o; o >>= 1) s += __shfl_xor_sync(0xffffffffu, s, o);
        if (lane == 0) {
            bool msk = (hn[m] == 0) && (m != L-1);
            sc[p] = msk ? -1e9f : s * (1.f / sqrtf((float)DH));
        }
    }
    __syncthreads();
    if (t < 2) {
        float mx = -1e30f;
        for (int m = 0; m < L; m++) mx = fmaxf(mx, sc[t*L + m]);
        float sum = 0.f;
        for (int m = 0; m < L; m++) { float e = expf(sc[t*L + m] - mx); sc[t*L + m] = e; sum += e; }
        float inv = 1.f / sum;
        for (int m = 0; m < L; m++) sc[t*L + m] *= inv;
    }
    __syncthreads();

    // weighted sums
    float4* wctx4 = (float4*)(wctx + (size_t)b*(2*DM));
    for (int i4 = t; i4 < 320; i4 += 256) {
        int h = i4 / 160, d4 = i4 - h*160;
        float4 acc = make_float4(0.f, 0.f, 0.f, 0.f);
        const float* scp = sc + h*L;
        #pragma unroll
        for (int m = 0; m < L; m++) {
            float a = scp[m];
            float4 r = rows4[m*160 + d4];
            acc.x += a*r.x; acc.y += a*r.y; acc.z += a*r.z; acc.w += a*r.w;
        }
        wctx4[i4] = acc;
    }
}

// ---------------- pooling attention: cp.async gather ----------------
#define ATT2_SMEM ((L*NB3 + NB3 + 32 + 256 + L) * 4 + 2*L*8 + L*4 + 16)
__global__ __launch_bounds__(128) void attn2_kernel(
    const int* __restrict__ nids, const int* __restrict__ hist_nids,
    const int* __restrict__ hist_eids, const float* __restrict__ hist_ts,
    const float* __restrict__ node_feat, const float* __restrict__ edge_feat,
    const float* __restrict__ time_w, const float* __restrict__ time_b,
    const float* __restrict__ qh2,
    float* __restrict__ A2)
{
    extern __shared__ float sm[];
    float* rows = sm;                          // [L][384]
    float* qs   = rows + L*NB3;                // [384]
    float* a    = qs + NB3;                    // [32]
    float* tw   = a + 32;                      // [128]
    float* tb   = tw + 128;                    // [128]
    float* dts  = tb + 128;                    // [20]
    const float** ptrs = (const float**)(((uintptr_t)(dts + L) + 15) & ~(uintptr_t)15);
    int*   hn   = (int*)(ptrs + 2*L);

    int b = blockIdx.x, t = threadIdx.x;
    int w = t >> 5, lane = t & 31;
    const uint32_t rows_u = smem_u32(rows);

    if (t < 128) { tw[t] = time_w[t]; tb[t] = time_b[t]; }
    if (t < L) {
        int hn_  = hist_nids[b*L + t];
        int eid_ = hist_eids[b*L + t];
        hn[t]  = hn_;
        dts[t] = hist_ts[b*L + L-1] - hist_ts[b*L + t];
        ptrs[0*L + t] = node_feat + (size_t)hn_ * NF;
        ptrs[1*L + t] = edge_feat + (size_t)eid_ * NF;
    }
    {
        float4* qs4 = (float4*)qs;
        const float4* src = (const float4*)(qh2 + (size_t)b*NB3);
        if (t < 96) qs4[t] = src[t];
    }
    __syncthreads();

    for (int task = w; task < 3*L; task += 4) {
        int seg = task / L, m = task - seg*L;
        if (seg < 2) {
            cp16(rows_u + (uint32_t)(m*NB3 + seg*128 + lane*4) * 4,
                 ptrs[seg*L + m] + lane*4);
        } else {
            float d = dts[m];
            float4 w4 = *(const float4*)(tw + lane*4);
            float4 b4 = *(const float4*)(tb + lane*4);
            float4 v;
            v.x = cosf(fmaf(d, w4.x, b4.x));
            v.y = cosf(fmaf(d, w4.y, b4.y));
            v.z = cosf(fmaf(d, w4.z, b4.z));
            v.w = cosf(fmaf(d, w4.w, b4.w));
            *(float4*)(rows + m*NB3 + seg*128 + lane*4) = v;
        }
    }
    asm volatile("cp.async.commit_group;" ::: "memory");
    asm volatile("cp.async.wait_group 0;" ::: "memory");
    __syncthreads();

    const float4* rows4 = (const float4*)rows;
    const float4* qs4   = (const float4*)qs;
    for (int l = w; l < L; l += 4) {
        const float4* rp = rows4 + l*96;
        float s = 0.f;
        #pragma unroll
        for (int k = 0; k < 3; k++) {
            float4 q = qs4[lane + k*32];
            float4 r = rp[lane + k*32];
            s += q.x*r.x + q.y*r.y + q.z*r.z + q.w*r.w;
        }
        #pragma unroll
        for (int o = 16; o; o >>= 1) s += __shfl_xor_sync(0xffffffffu, s, o);
        if (lane == 0) {
            bool msk = (hn[l] == 0) && (l != L-1);
            a[l] = msk ? -1e9f : s * (1.f / sqrtf((float)NF));
        }
    }
    __syncthreads();
    if (t == 0) {
        float mx = -1e30f;
        for (int l = 0; l < L; l++) mx = fmaxf(mx, a[l]);
        float sum = 0.f;
        for (int l = 0; l < L; l++) { float e = expf(a[l] - mx); a[l] = e; sum += e; }
        float inv = 1.f / sum;
        for (int l = 0; l < L; l++) a[l] *= inv;
    }
    __syncthreads();

    float4* A24 = (float4*)(A2 + (size_t)b*512);
    if (t < 96) {
        float4 acc = make_float4(0.f, 0.f, 0.f, 0.f);
        #pragma unroll
        for (int l = 0; l < L; l++) {
            float al = a[l];
            float4 r = rows4[l*96 + t];
            acc.x += al*r.x; acc.y += al*r.y; acc.z += al*r.z; acc.w += al*r.w;
        }
        A24[t] = acc;
    }
    if (t < 32) {
        const float4* nf4 = (const float4*)(node_feat + (size_t)nids[b]*NF);
        A24[96 + t] = nf4[t];
    }
}

// ---------------- GRU (float4) ----------------
__global__ void gru_kernel(const float* __restrict__ gi, const float* __restrict__ gh,
                           const float* __restrict__ hpl, float* __restrict__ hpr)
{
    int idx = blockIdx.x * blockDim.x + threadIdx.x;   // BS*32
    if (idx >= BS*32) return;
    int b = idx >> 5, f4 = idx & 31;
    const float4* gib = (const float4*)(gi + (size_t)b*3*NF);
    const float4* ghb = (const float4*)(gh + (size_t)b*3*NF);
    float4 ir = gib[f4],      hr = ghb[f4];
    float4 iz = gib[32 + f4], hz = ghb[32 + f4];
    float4 in_ = gib[64 + f4], hn_ = ghb[64 + f4];
    float4 hp = ((const float4*)(hpl + (size_t)b*NF))[f4];
    float4 o;
    {
        float r = 1.f/(1.f+expf(-(ir.x+hr.x)));
        float z = 1.f/(1.f+expf(-(iz.x+hz.x)));
        float n = tanhf(in_.x + r*hn_.x);
        o.x = (1.f-z)*n + z*hp.x;
    }
    {
        float r = 1.f/(1.f+expf(-(ir.y+hr.y)));
        float z = 1.f/(1.f+expf(-(iz.y+hz.y)));
        float n = tanhf(in_.y + r*hn_.y);
        o.y = (1.f-z)*n + z*hp.y;
    }
    {
        float r = 1.f/(1.f+expf(-(ir.z+hr.z)));
        float z = 1.f/(1.f+expf(-(iz.z+hz.z)));
        float n = tanhf(in_.z + r*hn_.z);
        o.z = (1.f-z)*n + z*hp.z;
    }
    {
        float r = 1.f/(1.f+expf(-(ir.w+hr.w)));
        float z = 1.f/(1.f+expf(-(iz.w+hz.w)));
        float n = tanhf(in_.w + r*hn_.w);
        o.w = (1.f-z)*n + z*hp.w;
    }
    ((float4*)(hpr + (size_t)b*NF))[f4] = o;
}

// ---------------- RK4 ODE: packed f32x2 FMA dot ----------------
#define ODE_SMEM ((128*129 + 2*128) * 4)
__global__ __launch_bounds__(128) void ode_kernel(
    const float* __restrict__ hpr, const float* __restrict__ ode_w,
    const float* __restrict__ ode_b, const float* __restrict__ tnode_w,
    const float* __restrict__ tnode_b, const float* __restrict__ hist_ts,
    float* __restrict__ out)
{
    extern __shared__ float sm[];
    float* Wsm = sm;
    float* vs  = sm + 128*129;           // 2 buffers of 128, 16B aligned
    int b = blockIdx.x, f = threadIdx.x;
    for (int i = f; i < NF*NF; i += 128) Wsm[(i >> 7)*129 + (i & 127)] = ode_w[i];
    float t0 = hist_ts[b*L + L-2];
    float t1 = hist_ts[b*L + L-1];
    float ratio = t1 - t0;
    float twf = tnode_w[f], tbf = tnode_b[f], obf = ode_b[f];
    float h0 = hpr[(size_t)b*NF + f];
    float z = h0;
    __syncthreads();
    // pack row f of W into 64 f32x2 registers
    unsigned long long w2[64];
    #pragma unroll
    for (int j = 0; j < 64; j++)
        w2[j] = packf2(Wsm[f*129 + 2*j], Wsm[f*129 + 2*j + 1]);
    __syncthreads();

    int buf = 0;
    auto feval = [&](float s, float zin) -> float {
        float* vb = vs + buf * 128;
        float t = fmaf(s, ratio, t0);
        vb[f] = zin + cosf(fmaf(t, twf, tbf));
        __syncthreads();
        unsigned long long a0 = 0ull, a1 = 0ull, a2 = 0ull, a3 = 0ull;
        const ulonglong2* vb2 = (const ulonglong2*)vb;   // broadcast reads
        #pragma unroll
        for (int j = 0; j < 32; j += 4) {
            ulonglong2 p0 = vb2[j];
            ulonglong2 p1 = vb2[j + 1];
            ulonglong2 p2 = vb2[j + 2];
            ulonglong2 p3 = vb2[j + 3];
            ffma2(a0, p0.x, w2[2*j]);     ffma2(a1, p0.y, w2[2*j + 1]);
            ffma2(a2, p1.x, w2[2*j + 2]); ffma2(a3, p1.y, w2[2*j + 3]);
            ffma2(a0, p2.x, w2[2*j + 4]); ffma2(a1, p2.y, w2[2*j + 5]);
            ffma2(a2, p3.x, w2[2*j + 6]); ffma2(a3, p3.y, w2[2*j + 7]);
        }
        buf ^= 1;
        float l0, h0_, l1, h1, l2, h2, l3, h3;
        unpackf2(l0, h0_, a0); unpackf2(l1, h1, a1);
        unpackf2(l2, h2, a2);  unpackf2(l3, h3, a3);
        float acc = obf + ((l0 + h0_) + (l1 + h1)) + ((l2 + h2) + (l3 + h3));
        return tanhf(acc) * ratio;
    };

    const float ds = 0.125f;
    for (int st = 0; st < 8; st++) {
        float s = st * ds;
        float k1 = feval(s,            z);
        float k2 = feval(s + 0.5f*ds,  z + 0.5f*ds*k1);
        float k3 = feval(s + 0.5f*ds,  z + 0.5f*ds*k2);
        float k4 = feval(s + ds,       z + ds*k3);
        z += ds * (1.f/6.f) * (k1 + 2.f*k2 + 2.f*k3 + k4);
    }
    out[(size_t)b*NF + f] = z;
    out[(size_t)BS*NF + (size_t)b*NF + f] = h0;
    if (f == 0) out[(size_t)2*BS*NF + b] = t1;
}

// ---------------- launch ----------------
extern "C" void kernel_launch(void* const* d_in, const int* in_sizes, int n_in,
                              void* d_out, int out_size)
{
    const int*   nids      = (const int*)  d_in[0];
    const int*   hist_nids = (const int*)  d_in[2];
    const int*   anon      = (const int*)  d_in[3];
    const int*   eids      = (const int*)  d_in[4];
    const float* hist_ts   = (const float*)d_in[5];
    const int*   dirs      = (const int*)  d_in[6];
    const float* node_feat = (const float*)d_in[7];
    const float* edge_feat = (const float*)d_in[8];
    const float* anony_emb = (const float*)d_in[9];
    const float* time_w    = (const float*)d_in[10];
    const float* time_b    = (const float*)d_in[11];
    const float* in_proj_w = (const float*)d_in[12];
    const float* in_proj_b = (const float*)d_in[13];
    const float* out_proj_w= (const float*)d_in[14];
    const float* out_proj_b= (const float*)d_in[15];
    const float* outfn_w   = (const float*)d_in[16];
    const float* outfn_b   = (const float*)d_in[17];
    const float* attn_wq   = (const float*)d_in[18];
    const float* attn_wk   = (const float*)d_in[19];
    const float* attn_wv   = (const float*)d_in[20];
    const float* merge_w   = (const float*)d_in[21];
    const float* merge_b   = (const float*)d_in[22];
    const float* gru_w_ih  = (const float*)d_in[23];
    const float* gru_w_hh  = (const float*)d_in[24];
    const float* gru_b_ih  = (const float*)d_in[25];
    const float* gru_b_hh  = (const float*)d_in[26];
    const float* ode_w     = (const float*)d_in[27];
    const float* ode_b     = (const float*)d_in[28];
    const float* tnode_w   = (const float*)d_in[29];
    const float* tnode_b   = (const float*)d_in[30];
    float* out = (float*)d_out;

    float *p_last, *p_wctx, *p_qh, *p_qh2, *p_A2, *p_hpl, *p_gi, *p_gh, *p_hpr,
          *p_q2, *p_G3, *p_b3, *p_WcmbT;
    cudaGetSymbolAddress((void**)&p_last,  g_last);
    cudaGetSymbolAddress((void**)&p_wctx,  g_wctx);
    cudaGetSymbolAddress((void**)&p_qh,    g_qh);
    cudaGetSymbolAddress((void**)&p_qh2,   g_qh2);
    cudaGetSymbolAddress((void**)&p_A2,    g_A2);
    cudaGetSymbolAddress((void**)&p_hpl,   g_hpl);
    cudaGetSymbolAddress((void**)&p_gi,    g_gi);
    cudaGetSymbolAddress((void**)&p_gh,    g_gh);
    cudaGetSymbolAddress((void**)&p_hpr,   g_hpr);
    cudaGetSymbolAddress((void**)&p_q2,    g_q2);
    cudaGetSymbolAddress((void**)&p_G3,    g_G3);
    cudaGetSymbolAddress((void**)&p_b3,    g_b3);
    cudaGetSymbolAddress((void**)&p_WcmbT, g_WcmbT);

    cudaFuncSetAttribute(gemm_tc<0,0>, cudaFuncAttributeMaxDynamicSharedMemorySize, GEMM_SMEM);
    cudaFuncSetAttribute(gemm_tc<1,0>, cudaFuncAttributeMaxDynamicSharedMemorySize, GEMM_SMEM);
    cudaFuncSetAttribute(gemm_tc<0,1>, cudaFuncAttributeMaxDynamicSharedMemorySize, GEMM_SMEM);
    cudaFuncSetAttribute(mha2_kernel, cudaFuncAttributeMaxDynamicSharedMemorySize, MHA2_SMEM);
    cudaFuncSetAttribute(attn2_kernel, cudaFuncAttributeMaxDynamicSharedMemorySize, ATT2_SMEM);
    cudaFuncSetAttribute(ode_kernel, cudaFuncAttributeMaxDynamicSharedMemorySize, ODE_SMEM);

    // --- prep ---
    prep_q<<<2, DM>>>(in_proj_w, in_proj_b, time_b, p_q2);
    prep_G<<<640, 256>>>(in_proj_w, in_proj_b, out_proj_w, out_proj_b,
                         outfn_w, outfn_b, attn_wq, attn_wv, merge_w,
                         p_G3, p_b3, p_WcmbT);
    bias_init<<<BS, NF>>>(p_b3, p_qh);

    // --- main pipeline ---
    mha2_kernel<<<BS, 256, MHA2_SMEM>>>(nids, hist_nids, anon, eids, hist_ts, dirs,
                                        node_feat, edge_feat, anony_emb, time_w, time_b,
                                        p_q2, p_wctx, p_last);
    gemm_tc<0,1><<<dim3(1, BS/128, 4), 256, GEMM_SMEM>>>(
        p_wctx, 2*DM, p_G3, 2*DM, nullptr, p_qh, NF, BS, NF, 320);
    gemm_tc<0,0><<<dim3(NB3/128, BS/128), 256, GEMM_SMEM>>>(
        p_qh, NF, attn_wk, NF, nullptr, p_qh2, NB3, BS, NB3, NF);
    attn2_kernel<<<BS, 128, ATT2_SMEM>>>(nids, hist_nids, eids, hist_ts,
                                         node_feat, edge_feat, time_w, time_b,
                                         p_qh2, p_A2);
    gemm_tc<1,0><<<dim3(1, BS/128), 256, GEMM_SMEM>>>(
        p_A2, 512, p_WcmbT, 512, merge_b, p_hpl, NF, BS, NF, 512);
    gemm_tc<0,0><<<dim3(3*NF/128, BS/128), 256, GEMM_SMEM>>>(
        p_last, DIN, gru_w_ih, DIN, gru_b_ih, p_gi, 3*NF, BS, 3*NF, DIN);
    gemm_tc<0,0><<<dim3(3*NF/128, BS/128), 256, GEMM_SMEM>>>(
        p_hpl, NF, gru_w_hh, NF, gru_b_hh, p_gh, 3*NF, BS, 3*NF, NF);
    gru_kernel<<<(BS*32 + 255)/256, 256>>>(p_gi, p_gh, p_hpl, p_hpr);
    ode_kernel<<<BS, 128, ODE_SMEM>>>(p_hpr, ode_w, ode_b, tnode_w, tnode_b, hist_ts, out);
}

// round 16
// speedup vs baseline: 1.4936x; 1.1243x over previous
#include <cuda_runtime.h>
#include <math.h>
#include <stdint.h>

#define BS   4096
#define L    20
#define NF   128
#define DM   640
#define DIN  512
#define DH   320
#define NB3  384

// ---------------- scratch ----------------
__device__ float g_last [BS*DIN];
__device__ float g_wctx [BS*2*DM];
__device__ float g_qh   [BS*NF];
__device__ float g_qh2  [BS*NB3];
__device__ float g_A2   [BS*512];
__device__ float g_hpl  [BS*NF];
__device__ float g_gi   [BS*3*NF];
__device__ float g_gh   [BS*3*NF];
__device__ float g_hpr  [BS*NF];
__device__ float g_q2   [2*DM];
__device__ float g_G3   [NF*2*DM];
__device__ float g_b3   [NF];
__device__ float g_WcmbT[NF*512];

__device__ __forceinline__ unsigned f2tf(float v) {
    unsigned r;
    asm("cvt.rna.tf32.f32 %0, %1;" : "=r"(r) : "f"(v));
    return r;
}
__device__ __forceinline__ uint32_t smem_u32(const void* p) {
    uint32_t a;
    asm("{ .reg .u64 t; cvta.to.shared.u64 t, %1; cvt.u32.u64 %0, t; }" : "=r"(a) : "l"(p));
    return a;
}
static __device__ __forceinline__ void cp16(uint32_t s, const void* g) {
    asm volatile("cp.async.cg.shared.global [%0], [%1], 16;" :: "r"(s), "l"(g));
}
__device__ __forceinline__ void mma_tf32(float c[4], unsigned a0, unsigned a1,
                                         unsigned a2, unsigned a3,
                                         unsigned b0, unsigned b1) {
    asm volatile(
        "mma.sync.aligned.m16n8k8.row.col.f32.tf32.tf32.f32 "
        "{%0,%1,%2,%3}, {%4,%5,%6,%7}, {%8,%9}, {%0,%1,%2,%3};"
        : "+f"(c[0]), "+f"(c[1]), "+f"(c[2]), "+f"(c[3])
        : "r"(a0), "r"(a1), "r"(a2), "r"(a3), "r"(b0), "r"(b1));
}
__device__ __forceinline__ void ffma2(unsigned long long& d, unsigned long long a,
                                      unsigned long long b) {
    asm("fma.rn.f32x2 %0, %1, %2, %0;" : "+l"(d) : "l"(a), "l"(b));
}
__device__ __forceinline__ unsigned long long packf2(float lo, float hi) {
    unsigned long long r;
    asm("mov.b64 %0, {%1, %2};" : "=l"(r) : "f"(lo), "f"(hi));
    return r;
}
__device__ __forceinline__ void unpackf2(float& lo, float& hi, unsigned long long v) {
    asm("mov.b64 {%0, %1}, %2;" : "=f"(lo), "=f"(hi) : "l"(v));
}

// ---------------- tf32 GEMM (proven core) ----------------
#define GS 3
#define STG_F (128*20)
#define GEMM_SMEM (GS*2*STG_F*4)

template<int ACT, int RED>
__global__ __launch_bounds__(256, 2) void gemm_tc(
    const float* __restrict__ A, int lda,
    const float* __restrict__ B, int ldb,
    const float* __restrict__ bias,
    float* __restrict__ C, int ldc,
    int M, int N, int K)
{
    extern __shared__ float smem[];
    const uint32_t smb = smem_u32(smem);
    const int bm = blockIdx.y * 128;
    const int bn = blockIdx.x * 128;
    const size_t kofs = (size_t)blockIdx.z * K;
    const int t  = threadIdx.x;
    const int lane = t & 31;
    const int wr = (t >> 5) >> 2;
    const int wc = (t >> 5) & 3;
    const int g = lane >> 2, tig = lane & 3;

    const int niter = K >> 4;
    const float* Abase = A + (size_t)bm * lda + kofs;
    const float* Bbase = B + (size_t)bn * ldb + kofs;

    auto load_stage = [&](int s, int c) {
        uint32_t as = smb + (uint32_t)(s * 2 * STG_F) * 4;
        uint32_t bs = as + STG_F * 4;
        const float* Ac = Abase + c * 16;
        const float* Bc = Bbase + c * 16;
        #pragma unroll
        for (int i = 0; i < 2; i++) {
            int id = i * 256 + t;
            int row = id >> 2, seg = id & 3;
            cp16(as + (uint32_t)(row * 20 + seg * 4) * 4, Ac + (size_t)row * lda + seg * 4);
            cp16(bs + (uint32_t)(row * 20 + seg * 4) * 4, Bc + (size_t)row * ldb + seg * 4);
        }
    };

    float acc[4][4][4] = {};

    #pragma unroll
    for (int s = 0; s < GS - 1; s++) {
        if (s < niter) load_stage(s, s);
        asm volatile("cp.async.commit_group;" ::: "memory");
    }

    for (int c = 0; c < niter; c++) {
        asm volatile("cp.async.wait_group %0;" :: "n"(GS - 2) : "memory");
        __syncthreads();
        if (c + GS - 1 < niter) load_stage((c + GS - 1) % GS, c + GS - 1);
        asm volatile("cp.async.commit_group;" ::: "memory");

        const float* As  = smem + (c % GS) * 2 * STG_F;
        const float* Bsm = As + STG_F;
        #pragma unroll
        for (int s8 = 0; s8 < 2; s8++) {
            const int kk = s8 * 8;
            unsigned af[4][4]; unsigned bf[4][2];
            #pragma unroll
            for (int i = 0; i < 4; i++) {
                int r0 = (wr * 64 + i * 16 + g) * 20 + kk + tig;
                af[i][0] = f2tf(As[r0]);
                af[i][1] = f2tf(As[r0 + 8 * 20]);
                af[i][2] = f2tf(As[r0 + 4]);
                af[i][3] = f2tf(As[r0 + 8 * 20 + 4]);
            }
            #pragma unroll
            for (int j = 0; j < 4; j++) {
                int n0 = (wc * 32 + j * 8 + g) * 20 + kk + tig;
                bf[j][0] = f2tf(Bsm[n0]);
                bf[j][1] = f2tf(Bsm[n0 + 4]);
            }
            #pragma unroll
            for (int i = 0; i < 4; i++)
                #pragma unroll
                for (int j = 0; j < 4; j++)
                    mma_tf32(acc[i][j], af[i][0], af[i][1], af[i][2], af[i][3],
                             bf[j][0], bf[j][1]);
        }
    }

    #pragma unroll
    for (int i = 0; i < 4; i++) {
        int row = bm + wr * 64 + i * 16 + g;
        #pragma unroll
        for (int j = 0; j < 4; j++) {
            int col = bn + wc * 32 + j * 8 + tig * 2;
            if (RED) {
                atomicAdd(C + (size_t)row * ldc + col,           acc[i][j][0]);
                atomicAdd(C + (size_t)row * ldc + col + 1,       acc[i][j][1]);
                atomicAdd(C + (size_t)(row + 8) * ldc + col,     acc[i][j][2]);
                atomicAdd(C + (size_t)(row + 8) * ldc + col + 1, acc[i][j][3]);
            } else {
                float b0 = bias ? bias[col] : 0.f;
                float b1 = bias ? bias[col + 1] : 0.f;
                float v00 = acc[i][j][0] + b0, v01 = acc[i][j][1] + b1;
                float v10 = acc[i][j][2] + b0, v11 = acc[i][j][3] + b1;
                if (ACT == 1) { v00 = tanhf(v00); v01 = tanhf(v01);
                                v10 = tanhf(v10); v11 = tanhf(v11); }
                *(float2*)(C + (size_t)row * ldc + col)       = make_float2(v00, v01);
                *(float2*)(C + (size_t)(row + 8) * ldc + col) = make_float2(v10, v11);
            }
        }
    }
}

__global__ void bias_init(const float* __restrict__ bias, float* __restrict__ C) {
    C[(size_t)blockIdx.x * NF + threadIdx.x] = bias[threadIdx.x];
}

// ---------------- prep_q ----------------
__global__ void prep_q(const float* __restrict__ ipw, const float* __restrict__ ipb,
                       const float* __restrict__ time_b, float* __restrict__ q2)
{
    __shared__ float tc[NF];
    __shared__ float q0s[DH];
    int h = blockIdx.x, t = threadIdx.x;
    if (t < NF) tc[t] = cosf(time_b[t]);
    __syncthreads();
    if (t < DH) {
        int e = h*DH + t;
        float acc = ipb[e];
        const float* row = ipw + (size_t)e * DM + DIN;
        for (int k = 0; k < NF; k++) acc += tc[k] * row[k];
        q0s[t] = acc;
    }
    __syncthreads();
    float acc = 0.f;
    const float* base = ipw + (size_t)(DM + h*DH) * DM + t;
    for (int d = 0; d < DH; d++) acc += q0s[d] * base[(size_t)d * DM];
    q2[h*DM + t] = acc;
}

// ---------------- prep_G ----------------
__global__ __launch_bounds__(256) void prep_G(
    const float* __restrict__ ipw, const float* __restrict__ ipb,
    const float* __restrict__ opw, const float* __restrict__ opb,
    const float* __restrict__ wf, const float* __restrict__ bf,
    const float* __restrict__ wq, const float* __restrict__ wv,
    const float* __restrict__ mw,
    float* __restrict__ G3, float* __restrict__ b3, float* __restrict__ WcmbT)
{
    int i = blockIdx.x, t = threadIdx.x;
    if (i >= 128) {
        int r = i - 128;
        if (r < 384) {
            if (t < NF) {
                float acc = 0.f;
                const float* wvr = wv + (size_t)r * NF;
                for (int k = 0; k < NF; k++) acc += wvr[k] * mw[k * NF + t];
                WcmbT[(size_t)t * 512 + r] = acc;
            }
        } else {
            int r2 = r - 384;
            if (t < NF) WcmbT[(size_t)t * 512 + 384 + r2] = mw[(NF + r2) * NF + t];
        }
        return;
    }
    __shared__ float wqc[NF];
    __shared__ float b1s[NF];
    __shared__ float t2[DM];
    __shared__ float gt[DM];
    __shared__ float red[256];
    if (t < NF) {
        wqc[t] = wq[t * NF + i];
        float acc = bf[t];
        const float* row = wf + (size_t)t * DM;
        for (int m = 0; m < DM; m++) acc += row[m] * opb[m];
        b1s[t] = acc;
    }
    __syncthreads();
    for (int j = t; j < DM; j += 256) {
        float acc = 0.f;
        for (int q = 0; q < NF; q++) acc += wqc[q] * wf[(size_t)q * DM + j];
        t2[j] = acc;
    }
    __syncthreads();
    for (int d = t; d < DM; d += 256) {
        float acc = 0.f;
        for (int m = 0; m < DM; m++) acc += t2[m] * opw[(size_t)m * DM + d];
        gt[d] = acc;
    }
    __syncthreads();
    for (int c = t; c < 2*DM; c += 256) {
        int h = c / DM, cc = c - h*DM;
        float acc = 0.f;
        const float* base = ipw + (size_t)(2*DM + h*DH) * DM + cc;
        const float* gth = gt + h*DH;
        for (int dd = 0; dd < DH; dd++) acc += gth[dd] * base[(size_t)dd * DM];
        G3[(size_t)i * (2*DM) + c] = acc;
    }
    float p = 0.f;
    for (int d = t; d < DM; d += 256) p += gt[d] * ipb[2*DM + d];
    if (t < NF) p += b1s[t] * wqc[t];
    red[t] = p;
    __syncthreads();
    if (t == 0) {
        float s = 0.f;
        for (int k = 0; k < 256; k++) s += red[k];
        b3[i] = s;
    }
}

// ---------------- MHA stage: cp.async gather, q2 via __ldg ----------------
#define MHA2_SMEM ((L*DM + 64 + 256 + L) * 4 + 4*L*8 + L*4 + 16)
__global__ __launch_bounds__(256) void mha2_kernel(
    const int* __restrict__ nids, const int* __restrict__ hist_nids,
    const int* __restrict__ anon_ids, const int* __restrict__ hist_eids,
    const float* __restrict__ hist_ts, const int* __restrict__ hist_dirs,
    const float* __restrict__ node_feat, const float* __restrict__ edge_feat,
    const float* __restrict__ anony_emb, const float* __restrict__ time_w,
    const float* __restrict__ time_b, const float* __restrict__ q2,
    float* __restrict__ wctx, float* __restrict__ last)
{
    extern __shared__ float sm[];
    float* rows = sm;
    float* sc   = rows + L*DM;
    float* tw   = sc + 64;
    float* tb   = tw + 128;
    float* dts  = tb + 128;
    const float** ptrs = (const float**)(((uintptr_t)(dts + L) + 15) & ~(uintptr_t)15);
    int*   hn   = (int*)(ptrs + 4*L);

    int b = blockIdx.x, t = threadIdx.x;
    int w = t >> 5, lane = t & 31;
    const uint32_t rows_u = smem_u32(rows);

    if (t < 128) { tw[t] = time_w[t]; tb[t] = time_b[t]; }
    if (t < L) {
        int hn_  = hist_nids[b*L + t];
        int eid_ = hist_eids[b*L + t];
        int aid_ = anon_ids[b*L + t];
        int dir_ = hist_dirs[b*L + t];
        int nid  = nids[b];
        hn[t]  = hn_;
        dts[t] = hist_ts[b*L + L-1] - hist_ts[b*L + t];
        ptrs[0*L + t] = node_feat + (size_t)(dir_ ? nid : hn_) * NF;
        ptrs[1*L + t] = node_feat + (size_t)(dir_ ? hn_ : nid) * NF;
        ptrs[2*L + t] = anony_emb + (size_t)aid_ * NF;
        ptrs[3*L + t] = edge_feat + (size_t)eid_ * NF;
    }
    __syncthreads();

    for (int task = w; task < 5*L; task += 8) {
        int seg = task / L, m = task - seg*L;
        if (seg < 4) {
            cp16(rows_u + (uint32_t)(m*DM + seg*128 + lane*4) * 4,
                 ptrs[seg*L + m] + lane*4);
        } else {
            float d = dts[m];
            float4 w4 = *(const float4*)(tw + lane*4);
            float4 b4 = *(const float4*)(tb + lane*4);
            float4 v;
            v.x = cosf(fmaf(d, w4.x, b4.x));
            v.y = cosf(fmaf(d, w4.y, b4.y));
            v.z = cosf(fmaf(d, w4.z, b4.z));
            v.w = cosf(fmaf(d, w4.w, b4.w));
            *(float4*)(rows + m*DM + seg*128 + lane*4) = v;
        }
    }
    asm volatile("cp.async.commit_group;" ::: "memory");
    asm volatile("cp.async.wait_group 0;" ::: "memory");
    __syncthreads();

    if (t < 128) {
        float4 v = *(float4*)&rows[(L-1)*DM + t*4];
        *(float4*)(last + (size_t)b*DIN + t*4) = v;
        *(float4*)&rows[(L-1)*DM + t*4] = make_float4(0.f, 0.f, 0.f, 0.f);
    }
    __syncthreads();

    const float4* rows4 = (const float4*)rows;
    const float4* q2g4  = (const float4*)q2;
    for (int p = w; p < 2*L; p += 8) {
        int h = p / L, m = p - h*L;
        const float4* rp = rows4 + m*160;
        float s = 0.f;
        #pragma unroll
        for (int k = 0; k < 5; k++) {
            float4 a = __ldg(&q2g4[h*160 + lane + k*32]);
            float4 r = rp[lane + k*32];
            s += a.x*r.x + a.y*r.y + a.z*r.z + a.w*r.w;
        }
        #pragma unroll
        for (int o = 16; o; o >>= 1) s += __shfl_xor_sync(0xffffffffu, s, o);
        if (lane == 0) {
            bool msk = (hn[m] == 0) && (m != L-1);
            sc[p] = msk ? -1e9f : s * (1.f / sqrtf((float)DH));
        }
    }
    __syncthreads();
    if (t < 2) {
        float mx = -1e30f;
        for (int m = 0; m < L; m++) mx = fmaxf(mx, sc[t*L + m]);
        float sum = 0.f;
        for (int m = 0; m < L; m++) { float e = expf(sc[t*L + m] - mx); sc[t*L + m] = e; sum += e; }
        float inv = 1.f / sum;
        for (int m = 0; m < L; m++) sc[t*L + m] *= inv;
    }
    __syncthreads();

    float4* wctx4 = (float4*)(wctx + (size_t)b*(2*DM));
    for (int i4 = t; i4 < 320; i4 += 256) {
        int h = i4 / 160, d4 = i4 - h*160;
        float4 acc = make_float4(0.f, 0.f, 0.f, 0.f);
        const float* scp = sc + h*L;
        #pragma unroll
        for (int m = 0; m < L; m++) {
            float a = scp[m];
            float4 r = rows4[m*160 + d4];
            acc.x += a*r.x; acc.y += a*r.y; acc.z += a*r.z; acc.w += a*r.w;
        }
        wctx4[i4] = acc;
    }
}

// ---------------- pooling attention: cp.async gather ----------------
#define ATT2_SMEM ((L*NB3 + NB3 + 32 + 256 + L) * 4 + 2*L*8 + L*4 + 16)
__global__ __launch_bounds__(128) void attn2_kernel(
    const int* __restrict__ nids, const int* __restrict__ hist_nids,
    const int* __restrict__ hist_eids, const float* __restrict__ hist_ts,
    const float* __restrict__ node_feat, const float* __restrict__ edge_feat,
    const float* __restrict__ time_w, const float* __restrict__ time_b,
    const float* __restrict__ qh2,
    float* __restrict__ A2)
{
    extern __shared__ float sm[];
    float* rows = sm;
    float* qs   = rows + L*NB3;
    float* a    = qs + NB3;
    float* tw   = a + 32;
    float* tb   = tw + 128;
    float* dts  = tb + 128;
    const float** ptrs = (const float**)(((uintptr_t)(dts + L) + 15) & ~(uintptr_t)15);
    int*   hn   = (int*)(ptrs + 2*L);

    int b = blockIdx.x, t = threadIdx.x;
    int w = t >> 5, lane = t & 31;
    const uint32_t rows_u = smem_u32(rows);

    if (t < 128) { tw[t] = time_w[t]; tb[t] = time_b[t]; }
    if (t < L) {
        int hn_  = hist_nids[b*L + t];
        int eid_ = hist_eids[b*L + t];
        hn[t]  = hn_;
        dts[t] = hist_ts[b*L + L-1] - hist_ts[b*L + t];
        ptrs[0*L + t] = node_feat + (size_t)hn_ * NF;
        ptrs[1*L + t] = edge_feat + (size_t)eid_ * NF;
    }
    {
        float4* qs4 = (float4*)qs;
        const float4* src = (const float4*)(qh2 + (size_t)b*NB3);
        if (t < 96) qs4[t] = src[t];
    }
    __syncthreads();

    for (int task = w; task < 3*L; task += 4) {
        int seg = task / L, m = task - seg*L;
        if (seg < 2) {
            cp16(rows_u + (uint32_t)(m*NB3 + seg*128 + lane*4) * 4,
                 ptrs[seg*L + m] + lane*4);
        } else {
            float d = dts[m];
            float4 w4 = *(const float4*)(tw + lane*4);
            float4 b4 = *(const float4*)(tb + lane*4);
            float4 v;
            v.x = cosf(fmaf(d, w4.x, b4.x));
            v.y = cosf(fmaf(d, w4.y, b4.y));
            v.z = cosf(fmaf(d, w4.z, b4.z));
            v.w = cosf(fmaf(d, w4.w, b4.w));
            *(float4*)(rows + m*NB3 + seg*128 + lane*4) = v;
        }
    }
    asm volatile("cp.async.commit_group;" ::: "memory");
    asm volatile("cp.async.wait_group 0;" ::: "memory");
    __syncthreads();

    const float4* rows4 = (const float4*)rows;
    const float4* qs4   = (const float4*)qs;
    for (int l = w; l < L; l += 4) {
        const float4* rp = rows4 + l*96;
        float s = 0.f;
        #pragma unroll
        for (int k = 0; k < 3; k++) {
            float4 q = qs4[lane + k*32];
            float4 r = rp[lane + k*32];
            s += q.x*r.x + q.y*r.y + q.z*r.z + q.w*r.w;
        }
        #pragma unroll
        for (int o = 16; o; o >>= 1) s += __shfl_xor_sync(0xffffffffu, s, o);
        if (lane == 0) {
            bool msk = (hn[l] == 0) && (l != L-1);
            a[l] = msk ? -1e9f : s * (1.f / sqrtf((float)NF));
        }
    }
    __syncthreads();
    if (t == 0) {
        float mx = -1e30f;
        for (int l = 0; l < L; l++) mx = fmaxf(mx, a[l]);
        float sum = 0.f;
        for (int l = 0; l < L; l++) { float e = expf(a[l] - mx); a[l] = e; sum += e; }
        float inv = 1.f / sum;
        for (int l = 0; l < L; l++) a[l] *= inv;
    }
    __syncthreads();

    float4* A24 = (float4*)(A2 + (size_t)b*512);
    if (t < 96) {
        float4 acc = make_float4(0.f, 0.f, 0.f, 0.f);
        #pragma unroll
        for (int l = 0; l < L; l++) {
            float al = a[l];
            float4 r = rows4[l*96 + t];
            acc.x += al*r.x; acc.y += al*r.y; acc.z += al*r.z; acc.w += al*r.w;
        }
        A24[t] = acc;
    }
    if (t < 32) {
        const float4* nf4 = (const float4*)(node_feat + (size_t)nids[b]*NF);
        A24[96 + t] = nf4[t];
    }
}

// ---------------- GRU (float4) ----------------
__global__ void gru_kernel(const float* __restrict__ gi, const float* __restrict__ gh,
                           const float* __restrict__ hpl, float* __restrict__ hpr)
{
    int idx = blockIdx.x * blockDim.x + threadIdx.x;
    if (idx >= BS*32) return;
    int b = idx >> 5, f4 = idx & 31;
    const float4* gib = (const float4*)(gi + (size_t)b*3*NF);
    const float4* ghb = (const float4*)(gh + (size_t)b*3*NF);
    float4 ir = gib[f4],      hr = ghb[f4];
    float4 iz = gib[32 + f4], hz = ghb[32 + f4];
    float4 in_ = gib[64 + f4], hn_ = ghb[64 + f4];
    float4 hp = ((const float4*)(hpl + (size_t)b*NF))[f4];
    float4 o;
    { float r = 1.f/(1.f+expf(-(ir.x+hr.x)));
      float z = 1.f/(1.f+expf(-(iz.x+hz.x)));
      float n = tanhf(in_.x + r*hn_.x);
      o.x = (1.f-z)*n + z*hp.x; }
    { float r = 1.f/(1.f+expf(-(ir.y+hr.y)));
      float z = 1.f/(1.f+expf(-(iz.y+hz.y)));
      float n = tanhf(in_.y + r*hn_.y);
      o.y = (1.f-z)*n + z*hp.y; }
    { float r = 1.f/(1.f+expf(-(ir.z+hr.z)));
      float z = 1.f/(1.f+expf(-(iz.z+hz.z)));
      float n = tanhf(in_.z + r*hn_.z);
      o.z = (1.f-z)*n + z*hp.z; }
    { float r = 1.f/(1.f+expf(-(ir.w+hr.w)));
      float z = 1.f/(1.f+expf(-(iz.w+hz.w)));
      float n = tanhf(in_.w + r*hn_.w);
      o.w = (1.f-z)*n + z*hp.w; }
    ((float4*)(hpr + (size_t)b*NF))[f4] = o;
}

// ---------------- RK4 ODE: packed f32x2 FMA dot ----------------
#define ODE_SMEM ((128*129 + 2*128) * 4)
__global__ __launch_bounds__(128) void ode_kernel(
    const float* __restrict__ hpr, const float* __restrict__ ode_w,
    const float* __restrict__ ode_b, const float* __restrict__ tnode_w,
    const float* __restrict__ tnode_b, const float* __restrict__ hist_ts,
    float* __restrict__ out)
{
    extern __shared__ float sm[];
    float* Wsm = sm;
    float* vs  = sm + 128*129;
    int b = blockIdx.x, f = threadIdx.x;
    for (int i = f; i < NF*NF; i += 128) Wsm[(i >> 7)*129 + (i & 127)] = ode_w[i];
    float t0 = hist_ts[b*L + L-2];
    float t1 = hist_ts[b*L + L-1];
    float ratio = t1 - t0;
    float twf = tnode_w[f], tbf = tnode_b[f], obf = ode_b[f];
    float h0 = hpr[(size_t)b*NF + f];
    float z = h0;
    __syncthreads();
    unsigned long long w2[64];
    #pragma unroll
    for (int j = 0; j < 64; j++)
        w2[j] = packf2(Wsm[f*129 + 2*j], Wsm[f*129 + 2*j + 1]);
    __syncthreads();

    int buf = 0;
    auto feval = [&](float s, float zin) -> float {
        float* vb = vs + buf * 128;
        float t = fmaf(s, ratio, t0);
        vb[f] = zin + cosf(fmaf(t, twf, tbf));
        __syncthreads();
        unsigned long long a0 = 0ull, a1 = 0ull, a2 = 0ull, a3 = 0ull;
        const ulonglong2* vb2 = (const ulonglong2*)vb;
        #pragma unroll
        for (int j = 0; j < 32; j += 4) {
            ulonglong2 p0 = vb2[j];
            ulonglong2 p1 = vb2[j + 1];
            ulonglong2 p2 = vb2[j + 2];
            ulonglong2 p3 = vb2[j + 3];
            ffma2(a0, p0.x, w2[2*j]);     ffma2(a1, p0.y, w2[2*j + 1]);
            ffma2(a2, p1.x, w2[2*j + 2]); ffma2(a3, p1.y, w2[2*j + 3]);
            ffma2(a0, p2.x, w2[2*j + 4]); ffma2(a1, p2.y, w2[2*j + 5]);
            ffma2(a2, p3.x, w2[2*j + 6]); ffma2(a3, p3.y, w2[2*j + 7]);
        }
        buf ^= 1;
        float l0, h0_, l1, h1, l2, h2, l3, h3;
        unpackf2(l0, h0_, a0); unpackf2(l1, h1, a1);
        unpackf2(l2, h2, a2);  unpackf2(l3, h3, a3);
        float acc = obf + ((l0 + h0_) + (l1 + h1)) + ((l2 + h2) + (l3 + h3));
        return tanhf(acc) * ratio;
    };

    const float ds = 0.125f;
    for (int st = 0; st < 8; st++) {
        float s = st * ds;
        float k1 = feval(s,            z);
        float k2 = feval(s + 0.5f*ds,  z + 0.5f*ds*k1);
        float k3 = feval(s + 0.5f*ds,  z + 0.5f*ds*k2);
        float k4 = feval(s + ds,       z + ds*k3);
        z += ds * (1.f/6.f) * (k1 + 2.f*k2 + 2.f*k3 + k4);
    }
    out[(size_t)b*NF + f] = z;
    out[(size_t)BS*NF + (size_t)b*NF + f] = h0;
    if (f == 0) out[(size_t)2*BS*NF + b] = t1;
}

// ---------------- launch (multi-stream DAG, legal capture fork) ----------------
extern "C" void kernel_launch(void* const* d_in, const int* in_sizes, int n_in,
                              void* d_out, int out_size)
{
    const int*   nids      = (const int*)  d_in[0];
    const int*   hist_nids = (const int*)  d_in[2];
    const int*   anon      = (const int*)  d_in[3];
    const int*   eids      = (const int*)  d_in[4];
    const float* hist_ts   = (const float*)d_in[5];
    const int*   dirs      = (const int*)  d_in[6];
    const float* node_feat = (const float*)d_in[7];
    const float* edge_feat = (const float*)d_in[8];
    const float* anony_emb = (const float*)d_in[9];
    const float* time_w    = (const float*)d_in[10];
    const float* time_b    = (const float*)d_in[11];
    const float* in_proj_w = (const float*)d_in[12];
    const float* in_proj_b = (const float*)d_in[13];
    const float* out_proj_w= (const float*)d_in[14];
    const float* out_proj_b= (const float*)d_in[15];
    const float* outfn_w   = (const float*)d_in[16];
    const float* outfn_b   = (const float*)d_in[17];
    const float* attn_wq   = (const float*)d_in[18];
    const float* attn_wk   = (const float*)d_in[19];
    const float* attn_wv   = (const float*)d_in[20];
    const float* merge_w   = (const float*)d_in[21];
    const float* merge_b   = (const float*)d_in[22];
    const float* gru_w_ih  = (const float*)d_in[23];
    const float* gru_w_hh  = (const float*)d_in[24];
    const float* gru_b_ih  = (const float*)d_in[25];
    const float* gru_b_hh  = (const float*)d_in[26];
    const float* ode_w     = (const float*)d_in[27];
    const float* ode_b     = (const float*)d_in[28];
    const float* tnode_w   = (const float*)d_in[29];
    const float* tnode_b   = (const float*)d_in[30];
    float* out = (float*)d_out;

    float *p_last, *p_wctx, *p_qh, *p_qh2, *p_A2, *p_hpl, *p_gi, *p_gh, *p_hpr,
          *p_q2, *p_G3, *p_b3, *p_WcmbT;
    cudaGetSymbolAddress((void**)&p_last,  g_last);
    cudaGetSymbolAddress((void**)&p_wctx,  g_wctx);
    cudaGetSymbolAddress((void**)&p_qh,    g_qh);
    cudaGetSymbolAddress((void**)&p_qh2,   g_qh2);
    cudaGetSymbolAddress((void**)&p_A2,    g_A2);
    cudaGetSymbolAddress((void**)&p_hpl,   g_hpl);
    cudaGetSymbolAddress((void**)&p_gi,    g_gi);
    cudaGetSymbolAddress((void**)&p_gh,    g_gh);
    cudaGetSymbolAddress((void**)&p_hpr,   g_hpr);
    cudaGetSymbolAddress((void**)&p_q2,    g_q2);
    cudaGetSymbolAddress((void**)&p_G3,    g_G3);
    cudaGetSymbolAddress((void**)&p_b3,    g_b3);
    cudaGetSymbolAddress((void**)&p_WcmbT, g_WcmbT);

    cudaFuncSetAttribute(gemm_tc<0,0>, cudaFuncAttributeMaxDynamicSharedMemorySize, GEMM_SMEM);
    cudaFuncSetAttribute(gemm_tc<1,0>, cudaFuncAttributeMaxDynamicSharedMemorySize, GEMM_SMEM);
    cudaFuncSetAttribute(gemm_tc<0,1>, cudaFuncAttributeMaxDynamicSharedMemorySize, GEMM_SMEM);
    cudaFuncSetAttribute(mha2_kernel, cudaFuncAttributeMaxDynamicSharedMemorySize, MHA2_SMEM);
    cudaFuncSetAttribute(attn2_kernel, cudaFuncAttributeMaxDynamicSharedMemorySize, ATT2_SMEM);
    cudaFuncSetAttribute(ode_kernel, cudaFuncAttributeMaxDynamicSharedMemorySize, ODE_SMEM);

    static cudaStream_t s1 = nullptr, s2 = nullptr;
    static cudaEvent_t  e_root = nullptr, e_prep = nullptr, e_mha = nullptr, e_gi = nullptr;
    if (!s1) {
        cudaStreamCreateWithFlags(&s1, cudaStreamNonBlocking);
        cudaStreamCreateWithFlags(&s2, cudaStreamNonBlocking);
        cudaEventCreateWithFlags(&e_root, cudaEventDisableTiming);
        cudaEventCreateWithFlags(&e_prep, cudaEventDisableTiming);
        cudaEventCreateWithFlags(&e_mha,  cudaEventDisableTiming);
        cudaEventCreateWithFlags(&e_gi,   cudaEventDisableTiming);
    }

    // FORK: side streams must join the capture via an event recorded on the
    // capturing (origin) stream BEFORE receiving any work.
    cudaEventRecord(e_root, 0);
    cudaStreamWaitEvent(s1, e_root, 0);
    cudaStreamWaitEvent(s2, e_root, 0);

    // side stream 1: weight prep (independent of mha2)
    prep_G<<<640, 256, 0, s1>>>(in_proj_w, in_proj_b, out_proj_w, out_proj_b,
                                outfn_w, outfn_b, attn_wq, attn_wv, merge_w,
                                p_G3, p_b3, p_WcmbT);
    bias_init<<<BS, NF, 0, s1>>>(p_b3, p_qh);
    cudaEventRecord(e_prep, s1);

    // main stream
    prep_q<<<2, DM>>>(in_proj_w, in_proj_b, time_b, p_q2);
    mha2_kernel<<<BS, 256, MHA2_SMEM>>>(nids, hist_nids, anon, eids, hist_ts, dirs,
                                        node_feat, edge_feat, anony_emb, time_w, time_b,
                                        p_q2, p_wctx, p_last);
    cudaEventRecord(e_mha, 0);

    // side stream 2: gi GEMM (needs only 'last' from mha2)
    cudaStreamWaitEvent(s2, e_mha, 0);
    gemm_tc<0,0><<<dim3(3*NF/128, BS/128), 256, GEMM_SMEM, s2>>>(
        p_last, DIN, gru_w_ih, DIN, gru_b_ih, p_gi, 3*NF, BS, 3*NF, DIN);
    cudaEventRecord(e_gi, s2);

    // main chain
    cudaStreamWaitEvent(0, e_prep, 0);
    gemm_tc<0,1><<<dim3(1, BS/128, 4), 256, GEMM_SMEM>>>(
        p_wctx, 2*DM, p_G3, 2*DM, nullptr, p_qh, NF, BS, NF, 320);
    gemm_tc<0,0><<<dim3(NB3/128, BS/128), 256, GEMM_SMEM>>>(
        p_qh, NF, attn_wk, NF, nullptr, p_qh2, NB3, BS, NB3, NF);
    attn2_kernel<<<BS, 128, ATT2_SMEM>>>(nids, hist_nids, eids, hist_ts,
                                         node_feat, edge_feat, time_w, time_b,
                                         p_qh2, p_A2);
    gemm_tc<1,0><<<dim3(1, BS/128), 256, GEMM_SMEM>>>(
        p_A2, 512, p_WcmbT, 512, merge_b, p_hpl, NF, BS, NF, 512);
    gemm_tc<0,0><<<dim3(3*NF/128, BS/128), 256, GEMM_SMEM>>>(
        p_hpl, NF, gru_w_hh, NF, gru_b_hh, p_gh, 3*NF, BS, 3*NF, NF);
    cudaStreamWaitEvent(0, e_gi, 0);
    gru_kernel<<<(BS*32 + 255)/256, 256>>>(p_gi, p_gh, p_hpl, p_hpr);
    ode_kernel<<<BS, 128, ODE_SMEM>>>(p_hpr, ode_w, ode_b, tnode_w, tnode_b, hist_ts, out);
}